// round 2
// baseline (speedup 1.0000x reference)
#include <cuda_runtime.h>
#include <math.h>

#define B_   8
#define M_   128
#define HID_ 256
#define NH_  8
#define D_   32

// ---------------- scratch (device globals: no allocations allowed) ----------
__device__ float g_q  [B_*M_*HID_];                 // 1 MB
__device__ float g_v  [B_*M_*HID_];                 // 1 MB
__device__ float g_nh [B_*M_*HID_];                 // 1 MB
__device__ float g_S  [B_*NH_*M_*M_];               // 4 MB
__device__ float g_msg[B_*NH_*M_*M_];               // 4 MB
__device__ float g_k  [(long long)B_*M_*M_*HID_];   // 134 MB

__device__ __forceinline__ float mishf(float x) {
    float sp = (x > 20.0f) ? x : log1pf(expf(x));
    return x * tanhf(sp);
}

// ---------------------------------------------------------------------------
// Generic 256-wide GEMM: C[r][c] = epi( sum_k A'[r][k] * W[c][k] + bias[c] )
//   MODE 0: A' = A,                     epi = identity        (q/v/k projections)
//   MODE 1: A' = A,                     epi = mish            (node output)
//   MODE 2: A'[r][k] = A[r][k]*sc[r][k>>5] (per-head message), epi = mish  (edge output)
// Tile: 64x64, BK=16, 256 threads, 4x4 per thread, float4 global loads.
// ---------------------------------------------------------------------------
template<int MODE>
__global__ __launch_bounds__(256) void gemm256(
    const float* __restrict__ A, const float* __restrict__ W,
    const float* __restrict__ bias, float* __restrict__ C,
    const float* __restrict__ msg)
{
    __shared__ float As[16][64];
    __shared__ float Ws[16][64];
    __shared__ float Ssc[64][8];

    const int tid = threadIdx.x;
    const long long rb = (long long)blockIdx.y * 64;
    const int cb = blockIdx.x * 64;

    if (MODE == 2) {
        // per-row, per-head scale: row r = ((b*128)+m)*128 + n, msg layout (b,h,m,n)
        for (int i = tid; i < 64*8; i += 256) {
            int r = i >> 3, h = i & 7;
            long long gr = rb + r;
            int n = (int)(gr & 127);
            int m = (int)((gr >> 7) & 127);
            int b = (int)(gr >> 14);
            Ssc[r][h] = msg[(((b*8 + h)*128 + m)*128) + n];
        }
        __syncthreads();
    }

    const int lr = tid >> 2;          // loader row/col 0..63
    const int lk = (tid & 3) << 2;    // loader k offset 0,4,8,12
    const int tr = tid & 15;          // compute thread row 0..15
    const int tc = tid >> 4;          // compute thread col 0..15

    float acc[4][4] = {};

    for (int k0 = 0; k0 < 256; k0 += 16) {
        float4 av = *reinterpret_cast<const float4*>(&A[(rb + lr)*256 + k0 + lk]);
        if (MODE == 2) {
            float s = Ssc[lr][(k0 + lk) >> 5];
            av.x *= s; av.y *= s; av.z *= s; av.w *= s;
        }
        As[lk+0][lr] = av.x; As[lk+1][lr] = av.y;
        As[lk+2][lr] = av.z; As[lk+3][lr] = av.w;

        float4 wv = *reinterpret_cast<const float4*>(&W[(long long)(cb + lr)*256 + k0 + lk]);
        Ws[lk+0][lr] = wv.x; Ws[lk+1][lr] = wv.y;
        Ws[lk+2][lr] = wv.z; Ws[lk+3][lr] = wv.w;
        __syncthreads();

        #pragma unroll
        for (int kk = 0; kk < 16; kk++) {
            float4 a4 = *reinterpret_cast<const float4*>(&As[kk][tr*4]);
            float4 w4 = *reinterpret_cast<const float4*>(&Ws[kk][tc*4]);
            float a[4] = {a4.x, a4.y, a4.z, a4.w};
            float w[4] = {w4.x, w4.y, w4.z, w4.w};
            #pragma unroll
            for (int i = 0; i < 4; i++)
                #pragma unroll
                for (int j = 0; j < 4; j++)
                    acc[i][j] += a[i]*w[j];
        }
        __syncthreads();
    }

    #pragma unroll
    for (int i = 0; i < 4; i++) {
        long long row = rb + tr*4 + i;
        #pragma unroll
        for (int j = 0; j < 4; j++) {
            int col = cb + tc*4 + j;
            float v = acc[i][j] + bias[col];
            if (MODE >= 1) v = mishf(v);
            C[row*256 + col] = v;
        }
    }
}

// ---------------------------------------------------------------------------
// S[b,h,m,n] = scale * sum_d q[b,m,h*32+d] * k[b,m,n,h*32+d]
// One block per (b,m); each warp sweeps n; 8 head-dots via shuffle reduce.
// ---------------------------------------------------------------------------
__global__ __launch_bounds__(256) void scores_kernel(
    const float* __restrict__ q, const float* __restrict__ k,
    float* __restrict__ S)
{
    const int bm = blockIdx.x;                // b*128 + m
    const int b = bm >> 7, m = bm & 127;
    __shared__ float qs[256];
    const int tid = threadIdx.x;
    qs[tid] = q[(long long)bm*256 + tid];
    __syncthreads();

    const int warp = tid >> 5, lane = tid & 31;
    const float scale = 0.17677669529663687f;   // 1/sqrt(32)
    const float* kbase = k + (long long)bm*128*256;

    for (int n = warp; n < 128; n += 8) {
        const float* kp = kbase + (long long)n*256;
        float p[8];
        #pragma unroll
        for (int h = 0; h < 8; h++) p[h] = kp[h*32 + lane] * qs[h*32 + lane];
        #pragma unroll
        for (int off = 16; off; off >>= 1)
            #pragma unroll
            for (int h = 0; h < 8; h++)
                p[h] += __shfl_xor_sync(0xffffffffu, p[h], off);
        if (lane < 8)
            S[((((long long)b*8 + lane)*128 + m)*128) + n] = p[lane]*scale;
    }
}

// ---------------------------------------------------------------------------
// Per (b,h): row+col softmax of S, message combine, distance decay,
// message write, and node_hidden = message @ v_head. One block per (b,h).
// Dynamic smem: S tile (128x129) + v slice (128x33).
// ---------------------------------------------------------------------------
__global__ __launch_bounds__(128) void message_kernel(
    const float* __restrict__ S, const float* __restrict__ v,
    const float* __restrict__ dist, const float* __restrict__ mask,
    const float* __restrict__ lam,
    float* __restrict__ msg, float* __restrict__ nh)
{
    extern __shared__ float sm[];
    float* Ss = sm;                // 128*129
    float* vs = sm + 128*129;      // 128*33
    __shared__ float msk[128];

    const int bh = blockIdx.x;
    const int b = bh >> 3, h = bh & 7;
    const int tid = threadIdx.x;   // 128 threads, thread = row m

    const float* Sg = S + (long long)bh*128*128;
    for (int idx = tid; idx < 128*128; idx += 128) {
        int r = idx >> 7, c = idx & 127;
        Ss[r*129 + c] = Sg[idx];
    }
    for (int idx = tid; idx < 128*32; idx += 128) {
        int n = idx >> 5, d = idx & 31;
        vs[n*33 + d] = v[((b*128 + n)*256) + h*32 + d];
    }
    msk[tid] = mask[b*128 + tid];
    __syncthreads();

    const float lamv = lam[0];
    const int m = tid;

    // row-m softmax stats over valid n
    float rmax = -1e30f;
    for (int n = 0; n < 128; n++)
        if (msk[n] != 0.0f) rmax = fmaxf(rmax, Ss[m*129 + n]);
    float rsum = 0.0f;
    for (int n = 0; n < 128; n++)
        if (msk[n] != 0.0f) rsum += expf(Ss[m*129 + n] - rmax);

    // column-m softmax stats over valid rows (in_attn denominator)
    float cmax = -1e30f;
    for (int n = 0; n < 128; n++)
        if (msk[n] != 0.0f) cmax = fmaxf(cmax, Ss[n*129 + m]);
    float csum = 0.0f;
    for (int n = 0; n < 128; n++)
        if (msk[n] != 0.0f) csum += expf(Ss[n*129 + m] - cmax);

    const float inv_rs = 1.0f / rsum;
    const float inv_cs = 1.0f / csum;

    float acc[32];
    #pragma unroll
    for (int d = 0; d < 32; d++) acc[d] = 0.0f;

    float* msgr = msg + ((long long)bh*128 + m)*128;
    const float* distr = dist + ((long long)b*128 + m)*128;

    for (int n = 0; n < 128; n++) {
        float eo = expf(Ss[m*129 + n] - rmax) * inv_rs;     // out_attn[m,n]
        float ei = expf(Ss[n*129 + m] - cmax) * inv_cs;     // in_attn[m,n]
        float t  = (n == m) ? ei : (eo + ei);               // diag term cancels eo
        float dmv = (msk[n] != 0.0f) ? expf(-lamv*distr[n]) : 0.0f;
        float mv = t * dmv;
        msgr[n] = mv;
        #pragma unroll
        for (int d = 0; d < 32; d++) acc[d] += mv * vs[n*33 + d];
    }

    float* nhr = nh + ((long long)(b*128 + m))*256 + h*32;
    #pragma unroll
    for (int d = 0; d < 32; d++) nhr[d] = acc[d];
}

// ---------------------------------------------------------------------------
extern "C" void kernel_launch(void* const* d_in, const int* in_sizes, int n_in,
                              void* d_out, int out_size)
{
    const float* node = (const float*)d_in[0];
    const float* edge = (const float*)d_in[1];
    const float* dist = (const float*)d_in[2];
    const float* mask = (const float*)d_in[3];
    const float* lam  = (const float*)d_in[4];
    const float* Wq   = (const float*)d_in[5];
    const float* bq   = (const float*)d_in[6];
    const float* Wk   = (const float*)d_in[7];
    const float* bk   = (const float*)d_in[8];
    const float* Wv   = (const float*)d_in[9];
    const float* bv   = (const float*)d_in[10];
    const float* Wn   = (const float*)d_in[11];
    const float* bn   = (const float*)d_in[12];
    const float* We   = (const float*)d_in[13];
    const float* be   = (const float*)d_in[14];

    float* out = (float*)d_out;
    float* node_out = out;                       // (B, M, HID)
    float* edge_out = out + B_*M_*HID_;          // (B, M, M, HID)

    float *q, *v, *k, *S, *msg, *nh;
    cudaGetSymbolAddress((void**)&q,   g_q);
    cudaGetSymbolAddress((void**)&v,   g_v);
    cudaGetSymbolAddress((void**)&k,   g_k);
    cudaGetSymbolAddress((void**)&S,   g_S);
    cudaGetSymbolAddress((void**)&msg, g_msg);
    cudaGetSymbolAddress((void**)&nh,  g_nh);

    const int smem = (128*129 + 128*33) * (int)sizeof(float);   // 82944 B
    cudaFuncSetAttribute(message_kernel,
                         cudaFuncAttributeMaxDynamicSharedMemorySize, smem);

    dim3 gsmall(4, (B_*M_)/64);          // (4, 16)
    dim3 gbig  (4, (B_*M_*M_)/64);       // (4, 2048)

    gemm256<0><<<gsmall, 256>>>(node, Wq, bq, q, nullptr);
    gemm256<0><<<gsmall, 256>>>(node, Wv, bv, v, nullptr);
    gemm256<0><<<gbig,   256>>>(edge, Wk, bk, k, nullptr);
    scores_kernel<<<B_*M_, 256>>>(q, k, S);
    message_kernel<<<B_*NH_, 128, smem>>>(S, v, dist, mask, lam, msg, nh);
    gemm256<1><<<gsmall, 256>>>(nh, Wn, bn, node_out, nullptr);
    gemm256<2><<<gbig,   256>>>(k, We, be, edge_out, msg);
}

// round 4
// speedup vs baseline: 3.4999x; 3.4999x over previous
#include <cuda_runtime.h>
#include <cuda_fp16.h>
#include <math.h>
#include <stdint.h>

#define B_   8
#define M_   128
#define HID_ 256
#define NH_  8
#define D_   32

// ---------------- scratch (device globals: no allocations allowed) ----------
__device__ float g_q  [B_*M_*HID_];
__device__ float g_v  [B_*M_*HID_];
__device__ float g_nh [B_*M_*HID_];
__device__ float g_S  [B_*NH_*M_*M_];
__device__ float g_msg[B_*NH_*M_*M_];
__device__ unsigned short g_k16 [(long long)B_*M_*M_*HID_];   // fp16 k (67 MB)
__device__ unsigned short g_Wk16[HID_*HID_];
__device__ unsigned short g_We16[HID_*HID_];

// ---------------------------- helpers ---------------------------------------
__device__ __forceinline__ uint32_t smem_u32(const void* p) {
    uint32_t a;
    asm("{ .reg .u64 t; cvta.to.shared.u64 t, %1; cvt.u32.u64 %0, t; }" : "=r"(a) : "l"(p));
    return a;
}
__device__ __forceinline__ void cp_async16(uint32_t dst, const void* src) {
    asm volatile("cp.async.cg.shared.global [%0], [%1], 16;" :: "r"(dst), "l"(src));
}
__device__ __forceinline__ void ldsm_x4(uint32_t* r, uint32_t addr) {
    asm volatile("ldmatrix.sync.aligned.m8n8.x4.shared.b16 {%0,%1,%2,%3}, [%4];"
        : "=r"(r[0]), "=r"(r[1]), "=r"(r[2]), "=r"(r[3]) : "r"(addr));
}
__device__ __forceinline__ void mma16816(float* c, const uint32_t* a, const uint32_t* b) {
    asm volatile("mma.sync.aligned.m16n8k16.row.col.f32.f16.f16.f32 "
        "{%0,%1,%2,%3}, {%4,%5,%6,%7}, {%8,%9}, {%0,%1,%2,%3};"
        : "+f"(c[0]), "+f"(c[1]), "+f"(c[2]), "+f"(c[3])
        : "r"(a[0]), "r"(a[1]), "r"(a[2]), "r"(a[3]), "r"(b[0]), "r"(b[1]));
}
__device__ __forceinline__ float mishf(float x) {
    if (x > 20.0f) return x;
    float t = __expf(x);
    float u = t * (t + 2.0f);
    return x * __fdividef(u, u + 2.0f);
}

// ---------------------------------------------------------------------------
// HMMA GEMM: C[131072 x 256] = epi( A'[131072 x 256] @ W16^T + bias )
//   MODE 0 (k-proj):   A = fp32 edge -> cvt fp16;  epi: +bias, store fp16
//   MODE 1 (edge-out): A = fp16 k, scaled per (row, head=k-iter) by msg;
//                      epi: +bias, mish, store fp32
// Tile: BM=128 x BN=256 x BK=32. 256 threads (8 warps, 2x4), warp tile 64x64.
// Smem rows padded to 40 halves (80B) -> conflict-free ldmatrix.
// ---------------------------------------------------------------------------
#define LDT 80            // bytes per padded smem row (40 halves)
#define OFF_SCALE 0       // 1024 floats (MODE 1)
#define OFF_BIAS  4096    // 256 floats
#define OFF_T     5120
#define ASZ (128*LDT)     // 10240
#define BSZ (256*LDT)     // 20480
#define SMEM_MMA (OFF_T + 2*(ASZ + BSZ))   // 66560

template<int MODE>
__global__ __launch_bounds__(256) void mma_gemm(
    const void* __restrict__ Asrc, const unsigned short* __restrict__ W16v,
    const float* __restrict__ bias, void* __restrict__ Cout,
    const float* __restrict__ msg)
{
    extern __shared__ __align__(128) char smem[];
    float* sclS  = (float*)(smem + OFF_SCALE);
    float* biasS = (float*)(smem + OFF_BIAS);
    const uint32_t sb = smem_u32(smem);
    const uint32_t stA0 = sb + OFF_T;
    const uint32_t stB0 = sb + OFF_T + ASZ;
    const uint32_t stA1 = sb + OFF_T + ASZ + BSZ;
    const uint32_t stB1 = sb + OFF_T + 2*ASZ + BSZ;
    const uint32_t stA[2] = { stA0, stA1 };
    const uint32_t stB[2] = { stB0, stB1 };

    const int tid  = threadIdx.x;
    const int lane = tid & 31, warp = tid >> 5;
    const int wm = warp >> 2, wn = warp & 3;
    const long long rb = (long long)blockIdx.x * 128;
    const __half* W16 = (const __half*)W16v;

    if (tid < 256) biasS[tid] = bias[tid];
    if (MODE == 1) {
        #pragma unroll
        for (int i = tid; i < 1024; i += 256) {
            int r = i >> 3, h = i & 7;
            long long gr = rb + r;
            int n = (int)(gr & 127), m = (int)((gr >> 7) & 127), b = (int)(gr >> 14);
            sclS[i] = msg[((((long long)b*8 + h)*128 + m)*128) + n];
        }
    }
    __syncthreads();

    // per-thread A/B loader coordinates
    const int r0 = tid >> 2;       // A rows 0..63
    const int r1 = r0 + 64;        // A rows 64..127
    const int ch = tid & 3;        // 16B chunk within 64B k-window

    float4 fa[4];   // MODE 0 staging (2 rows x 2 float4)
    uint4  ua[2];   // MODE 1 staging (2 rows x 8 halves)

#define LD_A(it) do {                                                          \
    if (MODE == 0) {                                                           \
        const float* Ap = (const float*)Asrc;                                  \
        const float4* q0 = (const float4*)(Ap + (rb + r0)*256 + (it)*32 + ch*8);\
        fa[0] = q0[0]; fa[1] = q0[1];                                          \
        const float4* q1 = (const float4*)(Ap + (rb + r1)*256 + (it)*32 + ch*8);\
        fa[2] = q1[0]; fa[3] = q1[1];                                          \
    } else {                                                                   \
        const uint4* Ap = (const uint4*)Asrc;                                  \
        ua[0] = Ap[(rb + r0)*32 + (it)*4 + ch];                                \
        ua[1] = Ap[(rb + r1)*32 + (it)*4 + ch];                                \
    } } while (0)

#define ST_A(it, buf) do {                                                     \
    if (MODE == 0) {                                                           \
        __half2 h0 = __floats2half2_rn(fa[0].x, fa[0].y);                      \
        __half2 h1 = __floats2half2_rn(fa[0].z, fa[0].w);                      \
        __half2 h2 = __floats2half2_rn(fa[1].x, fa[1].y);                      \
        __half2 h3 = __floats2half2_rn(fa[1].z, fa[1].w);                      \
        asm volatile("st.shared.v4.b32 [%0], {%1,%2,%3,%4};"                   \
            :: "r"(stA[buf] + r0*LDT + ch*16),                                 \
               "r"(*(uint32_t*)&h0), "r"(*(uint32_t*)&h1),                     \
               "r"(*(uint32_t*)&h2), "r"(*(uint32_t*)&h3));                    \
        h0 = __floats2half2_rn(fa[2].x, fa[2].y);                              \
        h1 = __floats2half2_rn(fa[2].z, fa[2].w);                              \
        h2 = __floats2half2_rn(fa[3].x, fa[3].y);                              \
        h3 = __floats2half2_rn(fa[3].z, fa[3].w);                              \
        asm volatile("st.shared.v4.b32 [%0], {%1,%2,%3,%4};"                   \
            :: "r"(stA[buf] + r1*LDT + ch*16),                                 \
               "r"(*(uint32_t*)&h0), "r"(*(uint32_t*)&h1),                     \
               "r"(*(uint32_t*)&h2), "r"(*(uint32_t*)&h3));                    \
    } else {                                                                   \
        __half2 s2 = __float2half2_rn(sclS[r0*8 + (it)]);                      \
        uint4 t0 = ua[0]; __half2* hp = (__half2*)&t0;                         \
        hp[0]=__hmul2(hp[0],s2); hp[1]=__hmul2(hp[1],s2);                      \
        hp[2]=__hmul2(hp[2],s2); hp[3]=__hmul2(hp[3],s2);                      \
        asm volatile("st.shared.v4.b32 [%0], {%1,%2,%3,%4};"                   \
            :: "r"(stA[buf] + r0*LDT + ch*16),                                 \
               "r"(t0.x), "r"(t0.y), "r"(t0.z), "r"(t0.w));                    \
        s2 = __float2half2_rn(sclS[r1*8 + (it)]);                              \
        uint4 t1 = ua[1]; hp = (__half2*)&t1;                                  \
        hp[0]=__hmul2(hp[0],s2); hp[1]=__hmul2(hp[1],s2);                      \
        hp[2]=__hmul2(hp[2],s2); hp[3]=__hmul2(hp[3],s2);                      \
        asm volatile("st.shared.v4.b32 [%0], {%1,%2,%3,%4};"                   \
            :: "r"(stA[buf] + r1*LDT + ch*16),                                 \
               "r"(t1.x), "r"(t1.y), "r"(t1.z), "r"(t1.w));                    \
    } } while (0)

#define CP_B(it, buf) do {                                                     \
    _Pragma("unroll")                                                          \
    for (int j = 0; j < 4; j++) {                                              \
        int n = (tid + j*256) >> 2;                                            \
        cp_async16(stB[buf] + n*LDT + ch*16, W16 + n*256 + (it)*32 + ch*8);    \
    } } while (0)

    float c[4][8][4];
    #pragma unroll
    for (int mt = 0; mt < 4; mt++)
        #pragma unroll
        for (int nt = 0; nt < 8; nt++)
            #pragma unroll
            for (int j = 0; j < 4; j++) c[mt][nt][j] = 0.0f;

    // ldmatrix per-lane address components
    const uint32_t a_off = (uint32_t)((wm*64 + (lane & 15))*LDT + (lane >> 4)*16);
    const uint32_t b_off = (uint32_t)((wn*64 + (lane & 7) + (lane >> 4)*8)*LDT
                                      + ((lane >> 3) & 1)*16);

    // ---------------- prologue
    LD_A(0);
    CP_B(0, 0);
    asm volatile("cp.async.commit_group;" ::: "memory");
    ST_A(0, 0);
    asm volatile("cp.async.wait_group 0;" ::: "memory");
    __syncthreads();

    // ---------------- main loop: 8 k-iters of 32
    #pragma unroll 1
    for (int it = 0; it < 8; it++) {
        const int cur = it & 1, nxt = cur ^ 1;
        if (it < 7) {
            LD_A(it + 1);
            CP_B(it + 1, nxt);
            asm volatile("cp.async.commit_group;" ::: "memory");
        }

        #pragma unroll
        for (int ks = 0; ks < 2; ks++) {
            uint32_t a[4][4], bfr[4][4];
            const uint32_t ab = stA[cur] + a_off + ks*32;
            #pragma unroll
            for (int mt = 0; mt < 4; mt++) ldsm_x4(a[mt], ab + mt*16*LDT);
            const uint32_t bb = stB[cur] + b_off + ks*32;
            #pragma unroll
            for (int ntp = 0; ntp < 4; ntp++) ldsm_x4(bfr[ntp], bb + ntp*16*LDT);
            #pragma unroll
            for (int mt = 0; mt < 4; mt++)
                #pragma unroll
                for (int nt = 0; nt < 8; nt++)
                    mma16816(c[mt][nt], a[mt], &bfr[nt >> 1][(nt & 1)*2]);
        }

        if (it < 7) {
            ST_A(it + 1, nxt);
            asm volatile("cp.async.wait_group 0;" ::: "memory");
        }
        __syncthreads();
    }

    // ---------------- epilogue
    const int mrow = lane >> 2;
    const int ncol = (lane & 3)*2;
    #pragma unroll
    for (int mt = 0; mt < 4; mt++) {
        #pragma unroll
        for (int nt = 0; nt < 8; nt++) {
            const int m = wm*64 + mt*16 + mrow;
            const int n = wn*64 + nt*8 + ncol;
            const float b0 = biasS[n], b1 = biasS[n+1];
            float* cc = c[mt][nt];
            if (MODE == 0) {
                __half2 h0 = __floats2half2_rn(cc[0] + b0, cc[1] + b1);
                __half2 h1 = __floats2half2_rn(cc[2] + b0, cc[3] + b1);
                unsigned short* o = (unsigned short*)Cout;
                *(uint32_t*)(o + (rb + m)*256 + n)     = *(uint32_t*)&h0;
                *(uint32_t*)(o + (rb + m + 8)*256 + n) = *(uint32_t*)&h1;
            } else {
                float* o = (float*)Cout;
                float2 o0 = { mishf(cc[0] + b0), mishf(cc[1] + b1) };
                float2 o1 = { mishf(cc[2] + b0), mishf(cc[3] + b1) };
                *(float2*)(o + (rb + m)*256 + n)     = o0;
                *(float2*)(o + (rb + m + 8)*256 + n) = o1;
            }
        }
    }
#undef LD_A
#undef ST_A
#undef CP_B
}

// ---------------------------------------------------------------------------
// W fp32 -> fp16 prep
// ---------------------------------------------------------------------------
__global__ void prep_w16(const float* __restrict__ Wk, const float* __restrict__ We,
                         unsigned short* __restrict__ Wk16, unsigned short* __restrict__ We16)
{
    int i = blockIdx.x * 256 + threadIdx.x;
    __half a = __float2half(Wk[i]);
    __half b = __float2half(We[i]);
    Wk16[i] = *(unsigned short*)&a;
    We16[i] = *(unsigned short*)&b;
}

// ---------------------------------------------------------------------------
// small SIMT GEMM (q/v/node_out): 64x64x16 tile, fp32
// ---------------------------------------------------------------------------
template<int MODE>   // 0 = identity, 1 = mish
__global__ __launch_bounds__(256) void gemm256(
    const float* __restrict__ A, const float* __restrict__ W,
    const float* __restrict__ bias, float* __restrict__ C)
{
    __shared__ float As[16][64];
    __shared__ float Ws[16][64];
    const int tid = threadIdx.x;
    const long long rb = (long long)blockIdx.y * 64;
    const int cb = blockIdx.x * 64;
    const int lr = tid >> 2, lk = (tid & 3) << 2;
    const int tr = tid & 15, tc = tid >> 4;
    float acc[4][4] = {};
    for (int k0 = 0; k0 < 256; k0 += 16) {
        float4 av = *reinterpret_cast<const float4*>(&A[(rb + lr)*256 + k0 + lk]);
        As[lk+0][lr] = av.x; As[lk+1][lr] = av.y; As[lk+2][lr] = av.z; As[lk+3][lr] = av.w;
        float4 wv = *reinterpret_cast<const float4*>(&W[(long long)(cb + lr)*256 + k0 + lk]);
        Ws[lk+0][lr] = wv.x; Ws[lk+1][lr] = wv.y; Ws[lk+2][lr] = wv.z; Ws[lk+3][lr] = wv.w;
        __syncthreads();
        #pragma unroll
        for (int kk = 0; kk < 16; kk++) {
            float4 a4 = *reinterpret_cast<const float4*>(&As[kk][tr*4]);
            float4 w4 = *reinterpret_cast<const float4*>(&Ws[kk][tc*4]);
            float a[4] = {a4.x, a4.y, a4.z, a4.w};
            float w[4] = {w4.x, w4.y, w4.z, w4.w};
            #pragma unroll
            for (int i = 0; i < 4; i++)
                #pragma unroll
                for (int j = 0; j < 4; j++) acc[i][j] += a[i]*w[j];
        }
        __syncthreads();
    }
    #pragma unroll
    for (int i = 0; i < 4; i++) {
        long long row = rb + tr*4 + i;
        #pragma unroll
        for (int j = 0; j < 4; j++) {
            int col = cb + tc*4 + j;
            float v = acc[i][j] + bias[col];
            if (MODE == 1) v = mishf(v);
            C[row*256 + col] = v;
        }
    }
}

// ---------------------------------------------------------------------------
// S[b,h,m,n] = scale * sum_d q[b,m,h*32+d] * k16[b,m,n,h*32+d]
// ---------------------------------------------------------------------------
__global__ __launch_bounds__(256) void scores_kernel(
    const float* __restrict__ q, const unsigned short* __restrict__ k16,
    float* __restrict__ S)
{
    const int bm = blockIdx.x;
    const int b = bm >> 7, m = bm & 127;
    __shared__ float qs[256];
    const int tid = threadIdx.x;
    qs[tid] = q[(long long)bm*256 + tid];
    __syncthreads();

    const int warp = tid >> 5, lane = tid & 31;
    const float scale = 0.17677669529663687f;
    const __half* kbase = (const __half*)k16 + (long long)bm*128*256;

    for (int n = warp; n < 128; n += 8) {
        const __half* kp = kbase + (long long)n*256;
        float p[8];
        #pragma unroll
        for (int h = 0; h < 8; h++) p[h] = __half2float(kp[h*32 + lane]) * qs[h*32 + lane];
        #pragma unroll
        for (int off = 16; off; off >>= 1)
            #pragma unroll
            for (int h = 0; h < 8; h++)
                p[h] += __shfl_xor_sync(0xffffffffu, p[h], off);
        if (lane < 8)
            S[((((long long)b*8 + lane)*128 + m)*128) + n] = p[lane]*scale;
    }
}

// ---------------------------------------------------------------------------
// softmax / message / node_hidden
// ---------------------------------------------------------------------------
__global__ __launch_bounds__(128) void message_kernel(
    const float* __restrict__ S, const float* __restrict__ v,
    const float* __restrict__ dist, const float* __restrict__ mask,
    const float* __restrict__ lam,
    float* __restrict__ msg, float* __restrict__ nh)
{
    extern __shared__ float sm[];
    float* Ss = sm;
    float* vs = sm + 128*129;
    __shared__ float msk[128];

    const int bh = blockIdx.x;
    const int b = bh >> 3, h = bh & 7;
    const int tid = threadIdx.x;

    const float* Sg = S + (long long)bh*128*128;
    for (int idx = tid; idx < 128*128; idx += 128) {
        int r = idx >> 7, c = idx & 127;
        Ss[r*129 + c] = Sg[idx];
    }
    for (int idx = tid; idx < 128*32; idx += 128) {
        int n = idx >> 5, d = idx & 31;
        vs[n*33 + d] = v[((b*128 + n)*256) + h*32 + d];
    }
    msk[tid] = mask[b*128 + tid];
    __syncthreads();

    const float lamv = lam[0];
    const int m = tid;

    float rmax = -1e30f, cmax = -1e30f;
    for (int n = 0; n < 128; n++)
        if (msk[n] != 0.0f) {
            rmax = fmaxf(rmax, Ss[m*129 + n]);
            cmax = fmaxf(cmax, Ss[n*129 + m]);
        }
    float rsum = 0.0f, csum = 0.0f;
    for (int n = 0; n < 128; n++)
        if (msk[n] != 0.0f) {
            rsum += __expf(Ss[m*129 + n] - rmax);
            csum += __expf(Ss[n*129 + m] - cmax);
        }
    const float inv_rs = 1.0f / rsum;
    const float inv_cs = 1.0f / csum;

    float acc[32];
    #pragma unroll
    for (int d = 0; d < 32; d++) acc[d] = 0.0f;

    float* msgr = msg + ((long long)bh*128 + m)*128;
    const float* distr = dist + ((long long)b*128 + m)*128;

    for (int n = 0; n < 128; n++) {
        float eo = __expf(Ss[m*129 + n] - rmax) * inv_rs;
        float ei = __expf(Ss[n*129 + m] - cmax) * inv_cs;
        float t  = (n == m) ? ei : (eo + ei);
        float dmv = (msk[n] != 0.0f) ? __expf(-lamv*distr[n]) : 0.0f;
        float mv = t * dmv;
        msgr[n] = mv;
        #pragma unroll
        for (int d = 0; d < 32; d++) acc[d] += mv * vs[n*33 + d];
    }

    float* nhr = nh + ((long long)(b*128 + m))*256 + h*32;
    #pragma unroll
    for (int d = 0; d < 32; d++) nhr[d] = acc[d];
}

// ---------------------------------------------------------------------------
extern "C" void kernel_launch(void* const* d_in, const int* in_sizes, int n_in,
                              void* d_out, int out_size)
{
    const float* node = (const float*)d_in[0];
    const float* edge = (const float*)d_in[1];
    const float* dist = (const float*)d_in[2];
    const float* mask = (const float*)d_in[3];
    const float* lam  = (const float*)d_in[4];
    const float* Wq   = (const float*)d_in[5];
    const float* bq   = (const float*)d_in[6];
    const float* Wk   = (const float*)d_in[7];
    const float* bk   = (const float*)d_in[8];
    const float* Wv   = (const float*)d_in[9];
    const float* bv   = (const float*)d_in[10];
    const float* Wn   = (const float*)d_in[11];
    const float* bn   = (const float*)d_in[12];
    const float* We   = (const float*)d_in[13];
    const float* be   = (const float*)d_in[14];

    float* out = (float*)d_out;
    float* node_out = out;
    float* edge_out = out + B_*M_*HID_;

    float *q, *v, *S, *msg, *nh;
    unsigned short *k16, *Wk16, *We16;
    cudaGetSymbolAddress((void**)&q,    g_q);
    cudaGetSymbolAddress((void**)&v,    g_v);
    cudaGetSymbolAddress((void**)&S,    g_S);
    cudaGetSymbolAddress((void**)&msg,  g_msg);
    cudaGetSymbolAddress((void**)&nh,   g_nh);
    cudaGetSymbolAddress((void**)&k16,  g_k16);
    cudaGetSymbolAddress((void**)&Wk16, g_Wk16);
    cudaGetSymbolAddress((void**)&We16, g_We16);

    const int smem_msg = (128*129 + 128*33) * (int)sizeof(float);
    cudaFuncSetAttribute(message_kernel,
                         cudaFuncAttributeMaxDynamicSharedMemorySize, smem_msg);
    cudaFuncSetAttribute(mma_gemm<0>,
                         cudaFuncAttributeMaxDynamicSharedMemorySize, SMEM_MMA);
    cudaFuncSetAttribute(mma_gemm<1>,
                         cudaFuncAttributeMaxDynamicSharedMemorySize, SMEM_MMA);

    dim3 gsmall(4, (B_*M_)/64);

    prep_w16<<<256, 256>>>(Wk, We, Wk16, We16);
    gemm256<0><<<gsmall, 256>>>(node, Wq, bq, q);
    gemm256<0><<<gsmall, 256>>>(node, Wv, bv, v);
    mma_gemm<0><<<1024, 256, SMEM_MMA>>>(edge, Wk16, bk, k16, nullptr);
    scores_kernel<<<B_*M_, 256>>>(q, k16, S);
    message_kernel<<<B_*NH_, 128, smem_msg>>>(S, v, dist, mask, lam, msg, nh);
    gemm256<1><<<gsmall, 256>>>(nh, Wn, bn, node_out);
    mma_gemm<1><<<1024, 256, SMEM_MMA>>>(k16, We16, be, edge_out, msg);
}

// round 5
// speedup vs baseline: 4.1880x; 1.1966x over previous
#include <cuda_runtime.h>
#include <cuda_fp16.h>
#include <math.h>
#include <stdint.h>

#define B_   8
#define M_   128
#define HID_ 256
#define NH_  8
#define D_   32

// ---------------- scratch (device globals: no allocations allowed) ----------
__device__ float g_q  [B_*M_*HID_];
__device__ float g_v  [B_*M_*HID_];
__device__ float g_nh [B_*M_*HID_];
__device__ float g_S  [B_*NH_*M_*M_];
__device__ float g_msg[B_*NH_*M_*M_];
__device__ unsigned short g_k16 [(long long)B_*M_*M_*HID_];   // fp16 k (67 MB)
__device__ unsigned short g_Wk16[HID_*HID_];
__device__ unsigned short g_We16[HID_*HID_];

// ---------------------------- helpers ---------------------------------------
__device__ __forceinline__ uint32_t smem_u32(const void* p) {
    uint32_t a;
    asm("{ .reg .u64 t; cvta.to.shared.u64 t, %1; cvt.u32.u64 %0, t; }" : "=r"(a) : "l"(p));
    return a;
}
__device__ __forceinline__ void cp_async16(uint32_t dst, const void* src) {
    asm volatile("cp.async.cg.shared.global [%0], [%1], 16;" :: "r"(dst), "l"(src));
}
__device__ __forceinline__ void ldsm_x4(uint32_t* r, uint32_t addr) {
    asm volatile("ldmatrix.sync.aligned.m8n8.x4.shared.b16 {%0,%1,%2,%3}, [%4];"
        : "=r"(r[0]), "=r"(r[1]), "=r"(r[2]), "=r"(r[3]) : "r"(addr));
}
__device__ __forceinline__ void mma16816(float* c, const uint32_t* a, const uint32_t* b) {
    asm volatile("mma.sync.aligned.m16n8k16.row.col.f32.f16.f16.f32 "
        "{%0,%1,%2,%3}, {%4,%5,%6,%7}, {%8,%9}, {%0,%1,%2,%3};"
        : "+f"(c[0]), "+f"(c[1]), "+f"(c[2]), "+f"(c[3])
        : "r"(a[0]), "r"(a[1]), "r"(a[2]), "r"(a[3]), "r"(b[0]), "r"(b[1]));
}
__device__ __forceinline__ float mishf(float x) {
    if (x > 20.0f) return x;
    float t = __expf(x);
    float u = t * (t + 2.0f);
    return x * __fdividef(u, u + 2.0f);
}

// ---------------------------------------------------------------------------
// HMMA GEMM: C[131072 x 256] = epi( A'[131072 x 256] @ W16^T + bias )
//   MODE 0 (k-proj):   A = fp32 edge -> cvt fp16; epi: +bias -> k16 (fp16)
//                      + FUSED SCORES: S[b,h,m,n] = scale * sum_col k*q
//   MODE 1 (edge-out): A = fp16 k scaled per (row, head=k-iter) by msg;
//                      epi: +bias, mish, store fp32
// Tile: BM=128 x BN=256 x BK=32. 256 threads (8 warps, 2x4), warp tile 64x64.
// B: 3-stage cp.async pipeline (wait_group 1). A: LDG->reg->STS double buffer.
// ---------------------------------------------------------------------------
#define LDT 80            // bytes per padded smem row (40 halves)
#define OFF_SCALE 0       // 1024 floats (MODE 1)
#define OFF_BIAS  4096    // 256 floats
#define OFF_QS    5120    // 256 floats (MODE 0)
#define OFF_SRED  6144    // 128*8 floats (MODE 0)
#define OFF_T     10240
#define ASZ (128*LDT)     // 10240
#define BSZ (256*LDT)     // 20480
#define SMEM_MMA (OFF_T + 2*ASZ + 3*BSZ)   // 92160

template<int MODE>
__global__ __launch_bounds__(256) void mma_gemm(
    const void* __restrict__ Asrc, const unsigned short* __restrict__ W16v,
    const float* __restrict__ bias, void* __restrict__ Cout,
    const float* __restrict__ msg,
    const float* __restrict__ qglob, float* __restrict__ Sglob)
{
    extern __shared__ __align__(128) char smem[];
    float* sclS  = (float*)(smem + OFF_SCALE);
    float* biasS = (float*)(smem + OFF_BIAS);
    float* qs    = (float*)(smem + OFF_QS);
    float* sred  = (float*)(smem + OFF_SRED);
    const uint32_t sb = smem_u32(smem);
    const uint32_t sA0 = sb + OFF_T;
    const uint32_t sA1 = sA0 + ASZ;
    const uint32_t sB0 = sA1 + ASZ;
    const uint32_t sB1 = sB0 + BSZ;
    const uint32_t sB2 = sB1 + BSZ;

    const int tid  = threadIdx.x;
    const int lane = tid & 31, warp = tid >> 5;
    const int wm = warp >> 2, wn = warp & 3;
    const long long rb = (long long)blockIdx.x * 128;
    const __half* W16 = (const __half*)W16v;

    biasS[tid] = bias[tid];
    if (MODE == 1) {
        #pragma unroll
        for (int i = tid; i < 1024; i += 256) {
            int r = i >> 3, h = i & 7;
            long long gr = rb + r;
            int n = (int)(gr & 127), m = (int)((gr >> 7) & 127), b = (int)(gr >> 14);
            sclS[i] = msg[((((long long)b*8 + h)*128 + m)*128) + n];
        }
    } else {
        // this CTA covers rows (b, m, n=0..127): (b, m) fixed
        int bq = (int)(rb >> 14), mq = (int)((rb >> 7) & 127);
        qs[tid] = qglob[((long long)bq*128 + mq)*256 + tid];
    }
    __syncthreads();

    // per-thread A/B loader coordinates
    const int r0 = tid >> 2;       // A rows 0..63
    const int r1 = r0 + 64;        // A rows 64..127
    const int ch = tid & 3;        // 16B chunk within 64B k-window

    float4 fa[4];   // MODE 0 staging (2 rows x 2 float4)
    uint4  ua[2];   // MODE 1 staging (2 rows x 8 halves)

#define LD_A(it) do {                                                          \
    if (MODE == 0) {                                                           \
        const float* Ap = (const float*)Asrc;                                  \
        const float4* q0 = (const float4*)(Ap + (rb + r0)*256 + (it)*32 + ch*8);\
        fa[0] = q0[0]; fa[1] = q0[1];                                          \
        const float4* q1 = (const float4*)(Ap + (rb + r1)*256 + (it)*32 + ch*8);\
        fa[2] = q1[0]; fa[3] = q1[1];                                          \
    } else {                                                                   \
        const uint4* Ap = (const uint4*)Asrc;                                  \
        ua[0] = Ap[(rb + r0)*32 + (it)*4 + ch];                                \
        ua[1] = Ap[(rb + r1)*32 + (it)*4 + ch];                                \
    } } while (0)

#define ST_A(it, sA) do {                                                      \
    if (MODE == 0) {                                                           \
        __half2 h0 = __floats2half2_rn(fa[0].x, fa[0].y);                      \
        __half2 h1 = __floats2half2_rn(fa[0].z, fa[0].w);                      \
        __half2 h2 = __floats2half2_rn(fa[1].x, fa[1].y);                      \
        __half2 h3 = __floats2half2_rn(fa[1].z, fa[1].w);                      \
        asm volatile("st.shared.v4.b32 [%0], {%1,%2,%3,%4};"                   \
            :: "r"((sA) + r0*LDT + ch*16),                                     \
               "r"(*(uint32_t*)&h0), "r"(*(uint32_t*)&h1),                     \
               "r"(*(uint32_t*)&h2), "r"(*(uint32_t*)&h3));                    \
        h0 = __floats2half2_rn(fa[2].x, fa[2].y);                              \
        h1 = __floats2half2_rn(fa[2].z, fa[2].w);                              \
        h2 = __floats2half2_rn(fa[3].x, fa[3].y);                              \
        h3 = __floats2half2_rn(fa[3].z, fa[3].w);                              \
        asm volatile("st.shared.v4.b32 [%0], {%1,%2,%3,%4};"                   \
            :: "r"((sA) + r1*LDT + ch*16),                                     \
               "r"(*(uint32_t*)&h0), "r"(*(uint32_t*)&h1),                     \
               "r"(*(uint32_t*)&h2), "r"(*(uint32_t*)&h3));                    \
    } else {                                                                   \
        __half2 s2 = __float2half2_rn(sclS[r0*8 + (it)]);                      \
        uint4 t0 = ua[0]; __half2* hp = (__half2*)&t0;                         \
        hp[0]=__hmul2(hp[0],s2); hp[1]=__hmul2(hp[1],s2);                      \
        hp[2]=__hmul2(hp[2],s2); hp[3]=__hmul2(hp[3],s2);                      \
        asm volatile("st.shared.v4.b32 [%0], {%1,%2,%3,%4};"                   \
            :: "r"((sA) + r0*LDT + ch*16),                                     \
               "r"(t0.x), "r"(t0.y), "r"(t0.z), "r"(t0.w));                    \
        s2 = __float2half2_rn(sclS[r1*8 + (it)]);                              \
        uint4 t1 = ua[1]; hp = (__half2*)&t1;                                  \
        hp[0]=__hmul2(hp[0],s2); hp[1]=__hmul2(hp[1],s2);                      \
        hp[2]=__hmul2(hp[2],s2); hp[3]=__hmul2(hp[3],s2);                      \
        asm volatile("st.shared.v4.b32 [%0], {%1,%2,%3,%4};"                   \
            :: "r"((sA) + r1*LDT + ch*16),                                     \
               "r"(t1.x), "r"(t1.y), "r"(t1.z), "r"(t1.w));                    \
    } } while (0)

#define CP_B(it, sB) do {                                                      \
    _Pragma("unroll")                                                          \
    for (int j = 0; j < 4; j++) {                                              \
        int n = (tid + j*256) >> 2;                                            \
        cp_async16((sB) + n*LDT + ch*16, W16 + n*256 + (it)*32 + ch*8);        \
    } } while (0)

    float c[4][8][4];
    #pragma unroll
    for (int mt = 0; mt < 4; mt++)
        #pragma unroll
        for (int nt = 0; nt < 8; nt++)
            #pragma unroll
            for (int j = 0; j < 4; j++) c[mt][nt][j] = 0.0f;

    // ldmatrix per-lane address components
    const uint32_t a_off = (uint32_t)((wm*64 + (lane & 15))*LDT + (lane >> 4)*16);
    const uint32_t b_off = (uint32_t)((wn*64 + (lane & 7) + (lane >> 4)*8)*LDT
                                      + ((lane >> 3) & 1)*16);

    // ---------------- prologue: prime A(0) and B(0), B(1)
    LD_A(0);
    CP_B(0, sB0);
    asm volatile("cp.async.commit_group;" ::: "memory");
    CP_B(1, sB1);
    asm volatile("cp.async.commit_group;" ::: "memory");
    ST_A(0, sA0);
    asm volatile("cp.async.wait_group 1;" ::: "memory");   // B(0) arrived
    __syncthreads();

    uint32_t sAcur = sA0, sAnxt = sA1;
    uint32_t sBcur = sB0, sBnxt = sB1, sBnn = sB2;

    // ---------------- main loop: 8 k-iters of 32
    #pragma unroll 1
    for (int it = 0; it < 8; it++) {
        if (it < 7) LD_A(it + 1);
        if (it < 6) {
            CP_B(it + 2, sBnn);
            asm volatile("cp.async.commit_group;" ::: "memory");
        }

        #pragma unroll
        for (int ks = 0; ks < 2; ks++) {
            uint32_t a[4][4], bfr[4][4];
            const uint32_t ab = sAcur + a_off + ks*32;
            #pragma unroll
            for (int mt = 0; mt < 4; mt++) ldsm_x4(a[mt], ab + mt*16*LDT);
            const uint32_t bb = sBcur + b_off + ks*32;
            #pragma unroll
            for (int ntp = 0; ntp < 4; ntp++) ldsm_x4(bfr[ntp], bb + ntp*16*LDT);
            #pragma unroll
            for (int mt = 0; mt < 4; mt++)
                #pragma unroll
                for (int nt = 0; nt < 8; nt++)
                    mma16816(c[mt][nt], a[mt], &bfr[nt >> 1][(nt & 1)*2]);
        }

        if (it < 7) ST_A(it + 1, sAnxt);
        if (it < 6) {
            asm volatile("cp.async.wait_group 1;" ::: "memory"); // B(it+1) done
        } else if (it == 6) {
            asm volatile("cp.async.wait_group 0;" ::: "memory"); // B(7) done
        }
        __syncthreads();

        uint32_t t = sAcur; sAcur = sAnxt; sAnxt = t;
        t = sBcur; sBcur = sBnxt; sBnxt = sBnn; sBnn = t;
    }

    // ---------------- epilogue
    const int mrow = lane >> 2;
    const int ncol = (lane & 3)*2;
    float p[2][8];
    if (MODE == 0) {
        #pragma unroll
        for (int hl = 0; hl < 2; hl++)
            #pragma unroll
            for (int rs = 0; rs < 8; rs++) p[hl][rs] = 0.0f;
    }

    #pragma unroll
    for (int mt = 0; mt < 4; mt++) {
        #pragma unroll
        for (int nt = 0; nt < 8; nt++) {
            const int m = wm*64 + mt*16 + mrow;
            const int n = wn*64 + nt*8 + ncol;
            const float b0 = biasS[n], b1 = biasS[n+1];
            float* cc = c[mt][nt];
            if (MODE == 0) {
                float v0 = cc[0] + b0, v1 = cc[1] + b1;
                float v2 = cc[2] + b0, v3 = cc[3] + b1;
                __half2 h0 = __floats2half2_rn(v0, v1);
                __half2 h1 = __floats2half2_rn(v2, v3);
                unsigned short* o = (unsigned short*)Cout;
                *(uint32_t*)(o + (rb + m)*256 + n)     = *(uint32_t*)&h0;
                *(uint32_t*)(o + (rb + m + 8)*256 + n) = *(uint32_t*)&h1;
                // fused scores partials: head = n/32, rows are n-positions
                const int hl = nt >> 2;
                const float q0 = qs[n], q1 = qs[n+1];
                p[hl][mt*2+0] += v0*q0 + v1*q1;
                p[hl][mt*2+1] += v2*q0 + v3*q1;
            } else {
                float* o = (float*)Cout;
                float2 o0 = { mishf(cc[0] + b0), mishf(cc[1] + b1) };
                float2 o1 = { mishf(cc[2] + b0), mishf(cc[3] + b1) };
                *(float2*)(o + (rb + m)*256 + n)     = o0;
                *(float2*)(o + (rb + m + 8)*256 + n) = o1;
            }
        }
    }

    if (MODE == 0) {
        // reduce partials over the 4 lanes sharing a row (lane^1, lane^2)
        #pragma unroll
        for (int o = 1; o <= 2; o <<= 1)
            #pragma unroll
            for (int hl = 0; hl < 2; hl++)
                #pragma unroll
                for (int rs = 0; rs < 8; rs++)
                    p[hl][rs] += __shfl_xor_sync(0xffffffffu, p[hl][rs], o);
        if ((lane & 3) == 0) {
            #pragma unroll
            for (int mt = 0; mt < 4; mt++)
                #pragma unroll
                for (int half = 0; half < 2; half++)
                    #pragma unroll
                    for (int hl = 0; hl < 2; hl++) {
                        int nloc = wm*64 + mt*16 + mrow + half*8;
                        sred[nloc*8 + wn*2 + hl] = p[hl][mt*2 + half];
                    }
        }
        __syncthreads();
        const int bq = (int)(rb >> 14), mq = (int)((rb >> 7) & 127);
        const float scale = 0.17677669529663687f;   // 1/sqrt(32)
        #pragma unroll
        for (int i = tid; i < 1024; i += 256) {
            int n = i >> 3, h = i & 7;
            Sglob[((((long long)bq*8 + h)*128 + mq)*128) + n] = sred[n*8 + h]*scale;
        }
    }
#undef LD_A
#undef ST_A
#undef CP_B
}

// ---------------------------------------------------------------------------
// W fp32 -> fp16 prep
// ---------------------------------------------------------------------------
__global__ void prep_w16(const float* __restrict__ Wk, const float* __restrict__ We,
                         unsigned short* __restrict__ Wk16, unsigned short* __restrict__ We16)
{
    int i = blockIdx.x * 256 + threadIdx.x;
    __half a = __float2half(Wk[i]);
    __half b = __float2half(We[i]);
    Wk16[i] = *(unsigned short*)&a;
    We16[i] = *(unsigned short*)&b;
}

// ---------------------------------------------------------------------------
// small SIMT GEMM body (q/v/node_out): 64x64x16 tile, fp32
// ---------------------------------------------------------------------------
template<int MODE>   // 0 = identity, 1 = mish
__device__ __forceinline__ void gemm_body(
    const float* __restrict__ A, const float* __restrict__ W,
    const float* __restrict__ bias, float* __restrict__ C,
    int bx, int by)
{
    __shared__ float As[16][64];
    __shared__ float Ws[16][64];
    const int tid = threadIdx.x;
    const long long rb = (long long)by * 64;
    const int cb = bx * 64;
    const int lr = tid >> 2, lk = (tid & 3) << 2;
    const int tr = tid & 15, tc = tid >> 4;
    float acc[4][4] = {};
    for (int k0 = 0; k0 < 256; k0 += 16) {
        float4 av = *reinterpret_cast<const float4*>(&A[(rb + lr)*256 + k0 + lk]);
        As[lk+0][lr] = av.x; As[lk+1][lr] = av.y; As[lk+2][lr] = av.z; As[lk+3][lr] = av.w;
        float4 wv = *reinterpret_cast<const float4*>(&W[(long long)(cb + lr)*256 + k0 + lk]);
        Ws[lk+0][lr] = wv.x; Ws[lk+1][lr] = wv.y; Ws[lk+2][lr] = wv.z; Ws[lk+3][lr] = wv.w;
        __syncthreads();
        #pragma unroll
        for (int kk = 0; kk < 16; kk++) {
            float4 a4 = *reinterpret_cast<const float4*>(&As[kk][tr*4]);
            float4 w4 = *reinterpret_cast<const float4*>(&Ws[kk][tc*4]);
            float a[4] = {a4.x, a4.y, a4.z, a4.w};
            float w[4] = {w4.x, w4.y, w4.z, w4.w};
            #pragma unroll
            for (int i = 0; i < 4; i++)
                #pragma unroll
                for (int j = 0; j < 4; j++) acc[i][j] += a[i]*w[j];
        }
        __syncthreads();
    }
    #pragma unroll
    for (int i = 0; i < 4; i++) {
        long long row = rb + tr*4 + i;
        #pragma unroll
        for (int j = 0; j < 4; j++) {
            int col = cb + tc*4 + j;
            float v = acc[i][j] + bias[col];
            if (MODE == 1) v = mishf(v);
            C[row*256 + col] = v;
        }
    }
}

__global__ __launch_bounds__(256) void proj_qv(
    const float* __restrict__ node,
    const float* __restrict__ Wq, const float* __restrict__ bq,
    const float* __restrict__ Wv, const float* __restrict__ bv,
    float* __restrict__ q, float* __restrict__ v)
{
    if (blockIdx.z == 0) gemm_body<0>(node, Wq, bq, q, blockIdx.x, blockIdx.y);
    else                 gemm_body<0>(node, Wv, bv, v, blockIdx.x, blockIdx.y);
}

__global__ __launch_bounds__(256) void node_out_gemm(
    const float* __restrict__ nh, const float* __restrict__ Wn,
    const float* __restrict__ bn, float* __restrict__ C)
{
    gemm_body<1>(nh, Wn, bn, C, blockIdx.x, blockIdx.y);
}

// ---------------------------------------------------------------------------
// softmax / message / node_hidden: one block per (b,h), 512 threads.
// 4-thread groups per row: stats via shfl; msg in smem; then nh over (m,d8).
// ---------------------------------------------------------------------------
#define VST 36
#define SMEM_MSG ((128*129 + 128*129 + 128*VST) * 4)

__global__ __launch_bounds__(512) void message_kernel(
    const float* __restrict__ S, const float* __restrict__ v,
    const float* __restrict__ dist, const float* __restrict__ mask,
    const float* __restrict__ lam,
    float* __restrict__ msg, float* __restrict__ nh)
{
    extern __shared__ float sm[];
    float* Ss   = sm;                  // 128 x 129
    float* msgS = sm + 128*129;        // 128 x 129
    float* vs   = msgS + 128*129;      // 128 x VST
    __shared__ float msk[128];

    const int bh = blockIdx.x;
    const int b = bh >> 3, h = bh & 7;
    const int tid = threadIdx.x;

    const float* Sg = S + (long long)bh*128*128;
    for (int idx = tid; idx < 128*128; idx += 512)
        Ss[(idx >> 7)*129 + (idx & 127)] = Sg[idx];
    for (int idx = tid; idx < 128*32; idx += 512)
        vs[(idx >> 5)*VST + (idx & 31)] = v[((b*128 + (idx >> 5))*256) + h*32 + (idx & 31)];
    if (tid < 128) msk[tid] = mask[b*128 + tid];
    __syncthreads();

    const int g = tid >> 2, qq = tid & 3, n0 = qq*32;
    const float lamv = lam[0];

    // row-g stats over this quarter, combine across the 4-lane group
    float rmax = -1e30f, cmax = -1e30f;
    #pragma unroll 4
    for (int i = 0; i < 32; i++) {
        int n = n0 + i;
        if (msk[n] != 0.0f) {
            rmax = fmaxf(rmax, Ss[g*129 + n]);
            cmax = fmaxf(cmax, Ss[n*129 + g]);
        }
    }
    rmax = fmaxf(rmax, __shfl_xor_sync(0xffffffffu, rmax, 1));
    rmax = fmaxf(rmax, __shfl_xor_sync(0xffffffffu, rmax, 2));
    cmax = fmaxf(cmax, __shfl_xor_sync(0xffffffffu, cmax, 1));
    cmax = fmaxf(cmax, __shfl_xor_sync(0xffffffffu, cmax, 2));

    float rsum = 0.0f, csum = 0.0f;
    #pragma unroll 4
    for (int i = 0; i < 32; i++) {
        int n = n0 + i;
        if (msk[n] != 0.0f) {
            rsum += __expf(Ss[g*129 + n] - rmax);
            csum += __expf(Ss[n*129 + g] - cmax);
        }
    }
    rsum += __shfl_xor_sync(0xffffffffu, rsum, 1);
    rsum += __shfl_xor_sync(0xffffffffu, rsum, 2);
    csum += __shfl_xor_sync(0xffffffffu, csum, 1);
    csum += __shfl_xor_sync(0xffffffffu, csum, 2);
    const float inv_rs = 1.0f / rsum, inv_cs = 1.0f / csum;

    // msg for row g, this quarter of n
    const float* distr = dist + ((long long)b*128 + g)*128;
    float* msgr = msg + ((long long)bh*128 + g)*128;
    #pragma unroll 4
    for (int i = 0; i < 32; i++) {
        int n = n0 + i;
        float eo = __expf(Ss[g*129 + n] - rmax) * inv_rs;
        float ei = __expf(Ss[n*129 + g] - cmax) * inv_cs;
        float t  = (n == g) ? ei : (eo + ei);
        float dm = (msk[n] != 0.0f) ? __expf(-lamv*distr[n]) : 0.0f;
        float mv = t * dm;
        msgS[g*129 + n] = mv;
        msgr[n] = mv;
    }
    __syncthreads();

    // node_hidden: m = tid>>2 owns d-octet (tid&3)*8
    const int m = tid >> 2, d0 = (tid & 3)*8;
    float acc[8];
    #pragma unroll
    for (int j = 0; j < 8; j++) acc[j] = 0.0f;
    #pragma unroll 4
    for (int n = 0; n < 128; n++) {
        float mv = msgS[m*129 + n];
        float4 a = *(const float4*)&vs[n*VST + d0];
        float4 bb = *(const float4*)&vs[n*VST + d0 + 4];
        acc[0] += mv*a.x;  acc[1] += mv*a.y;  acc[2] += mv*a.z;  acc[3] += mv*a.w;
        acc[4] += mv*bb.x; acc[5] += mv*bb.y; acc[6] += mv*bb.z; acc[7] += mv*bb.w;
    }
    float* nhr = nh + ((long long)(b*128 + m))*256 + h*32 + d0;
    *(float4*)nhr       = make_float4(acc[0], acc[1], acc[2], acc[3]);
    *(float4*)(nhr + 4) = make_float4(acc[4], acc[5], acc[6], acc[7]);
}

// ---------------------------------------------------------------------------
extern "C" void kernel_launch(void* const* d_in, const int* in_sizes, int n_in,
                              void* d_out, int out_size)
{
    const float* node = (const float*)d_in[0];
    const float* edge = (const float*)d_in[1];
    const float* dist = (const float*)d_in[2];
    const float* mask = (const float*)d_in[3];
    const float* lam  = (const float*)d_in[4];
    const float* Wq   = (const float*)d_in[5];
    const float* bq   = (const float*)d_in[6];
    const float* Wk   = (const float*)d_in[7];
    const float* bk   = (const float*)d_in[8];
    const float* Wv   = (const float*)d_in[9];
    const float* bv   = (const float*)d_in[10];
    const float* Wn   = (const float*)d_in[11];
    const float* bn   = (const float*)d_in[12];
    const float* We   = (const float*)d_in[13];
    const float* be   = (const float*)d_in[14];

    float* out = (float*)d_out;
    float* node_out = out;
    float* edge_out = out + B_*M_*HID_;

    float *q, *v, *S, *msg, *nh;
    unsigned short *k16, *Wk16, *We16;
    cudaGetSymbolAddress((void**)&q,    g_q);
    cudaGetSymbolAddress((void**)&v,    g_v);
    cudaGetSymbolAddress((void**)&S,    g_S);
    cudaGetSymbolAddress((void**)&msg,  g_msg);
    cudaGetSymbolAddress((void**)&nh,   g_nh);
    cudaGetSymbolAddress((void**)&k16,  g_k16);
    cudaGetSymbolAddress((void**)&Wk16, g_Wk16);
    cudaGetSymbolAddress((void**)&We16, g_We16);

    cudaFuncSetAttribute(message_kernel,
                         cudaFuncAttributeMaxDynamicSharedMemorySize, SMEM_MSG);
    cudaFuncSetAttribute(mma_gemm<0>,
                         cudaFuncAttributeMaxDynamicSharedMemorySize, SMEM_MMA);
    cudaFuncSetAttribute(mma_gemm<1>,
                         cudaFuncAttributeMaxDynamicSharedMemorySize, SMEM_MMA);

    prep_w16<<<256, 256>>>(Wk, We, Wk16, We16);
    proj_qv<<<dim3(4, 16, 2), 256>>>(node, Wq, bq, Wv, bv, q, v);
    mma_gemm<0><<<1024, 256, SMEM_MMA>>>(edge, Wk16, bk, k16, nullptr, q, S);
    message_kernel<<<B_*NH_, 512, SMEM_MSG>>>(S, v, dist, mask, lam, msg, nh);
    node_out_gemm<<<dim3(4, 16), 256>>>(nh, Wn, bn, node_out);
    mma_gemm<1><<<1024, 256, SMEM_MMA>>>(k16, We16, be, edge_out, msg, nullptr, nullptr);
}

// round 6
// speedup vs baseline: 4.5711x; 1.0915x over previous
#include <cuda_runtime.h>
#include <cuda_fp16.h>
#include <math.h>
#include <stdint.h>

#define B_   8
#define M_   128
#define HID_ 256
#define NH_  8
#define D_   32

// ---------------- scratch (device globals: no allocations allowed) ----------
__device__ float g_q  [B_*M_*HID_];
__device__ float g_v  [B_*M_*HID_];
__device__ float g_nh [B_*M_*HID_];
__device__ float g_S  [B_*NH_*M_*M_];
__device__ float g_msg[B_*M_*M_*NH_];               // layout [(b,m,n), h]
__device__ float g_dm [B_*M_*M_];                   // mask * exp(-lam*dist)
__device__ unsigned short g_k16 [(long long)B_*M_*M_*HID_];   // fp16 k (67 MB)
__device__ unsigned short g_Wk16[HID_*HID_];
__device__ unsigned short g_We16[HID_*HID_];

// ---------------------------- helpers ---------------------------------------
__device__ __forceinline__ uint32_t smem_u32(const void* p) {
    uint32_t a;
    asm("{ .reg .u64 t; cvta.to.shared.u64 t, %1; cvt.u32.u64 %0, t; }" : "=r"(a) : "l"(p));
    return a;
}
__device__ __forceinline__ void cp_async16(uint32_t dst, const void* src) {
    asm volatile("cp.async.cg.shared.global [%0], [%1], 16;" :: "r"(dst), "l"(src));
}
__device__ __forceinline__ void ldsm_x4(uint32_t* r, uint32_t addr) {
    asm volatile("ldmatrix.sync.aligned.m8n8.x4.shared.b16 {%0,%1,%2,%3}, [%4];"
        : "=r"(r[0]), "=r"(r[1]), "=r"(r[2]), "=r"(r[3]) : "r"(addr));
}
__device__ __forceinline__ void mma16816(float* c, const uint32_t* a, const uint32_t* b) {
    asm volatile("mma.sync.aligned.m16n8k16.row.col.f32.f16.f16.f32 "
        "{%0,%1,%2,%3}, {%4,%5,%6,%7}, {%8,%9}, {%0,%1,%2,%3};"
        : "+f"(c[0]), "+f"(c[1]), "+f"(c[2]), "+f"(c[3])
        : "r"(a[0]), "r"(a[1]), "r"(a[2]), "r"(a[3]), "r"(b[0]), "r"(b[1]));
}
__device__ __forceinline__ float mishf(float x) {
    if (x > 20.0f) return x;
    float t = __expf(x);
    float u = t * (t + 2.0f);
    return x * __fdividef(u, u + 2.0f);
}

// ---------------------------------------------------------------------------
// HMMA GEMM: C[131072 x 256] = epi( A'[131072 x 256] @ W16^T + bias )
//   MODE 0 (k-proj):   A = fp32 edge -> cvt fp16; epi: +bias -> k16 (fp16)
//                      + FUSED SCORES: S[b,h,m,n] = scale * sum_col k*q
//   MODE 1 (edge-out): A = fp16 k scaled per (row, head=k-iter) by msg_t;
//                      epi: +bias, mish, store fp32
// Tile: BM=128 x BN=256 x BK=32. 256 threads (8 warps, 2x4), warp tile 64x64.
// B: 3-stage cp.async pipeline (wait_group 1). A: LDG->reg->STS double buffer.
// ---------------------------------------------------------------------------
#define LDT 80            // bytes per padded smem row (40 halves)
#define OFF_SCALE 0       // 1024 floats (MODE 1)
#define OFF_BIAS  4096    // 256 floats
#define OFF_QS    5120    // 256 floats (MODE 0)
#define OFF_SRED  6144    // 128*8 floats (MODE 0)
#define OFF_T     10240
#define ASZ (128*LDT)     // 10240
#define BSZ (256*LDT)     // 20480
#define SMEM_MMA (OFF_T + 2*ASZ + 3*BSZ)   // 92160

template<int MODE>
__global__ __launch_bounds__(256) void mma_gemm(
    const void* __restrict__ Asrc, const unsigned short* __restrict__ W16v,
    const float* __restrict__ bias, void* __restrict__ Cout,
    const float* __restrict__ msg_t,
    const float* __restrict__ qglob, float* __restrict__ Sglob)
{
    extern __shared__ __align__(128) char smem[];
    float* sclS  = (float*)(smem + OFF_SCALE);
    float* biasS = (float*)(smem + OFF_BIAS);
    float* qs    = (float*)(smem + OFF_QS);
    float* sred  = (float*)(smem + OFF_SRED);
    const uint32_t sb = smem_u32(smem);
    const uint32_t sA0 = sb + OFF_T;
    const uint32_t sA1 = sA0 + ASZ;
    const uint32_t sB0 = sA1 + ASZ;
    const uint32_t sB1 = sB0 + BSZ;
    const uint32_t sB2 = sB1 + BSZ;

    const int tid  = threadIdx.x;
    const int lane = tid & 31, warp = tid >> 5;
    const int wm = warp >> 2, wn = warp & 3;
    const long long rb = (long long)blockIdx.x * 128;
    const __half* W16 = (const __half*)W16v;

    biasS[tid] = bias[tid];
    if (MODE == 1) {
        // msg_t layout [(b,m,n), h]: rows rb..rb+127 x 8 heads, contiguous
        const float4* ms = (const float4*)(msg_t + rb*8);
        float4* ds = (float4*)sclS;
        ds[tid] = ms[tid];
    } else {
        // this CTA covers rows (b, m, n=0..127): (b, m) fixed
        int bq = (int)(rb >> 14), mq = (int)((rb >> 7) & 127);
        qs[tid] = qglob[((long long)bq*128 + mq)*256 + tid];
    }
    __syncthreads();

    // per-thread A/B loader coordinates
    const int r0 = tid >> 2;       // A rows 0..63
    const int r1 = r0 + 64;        // A rows 64..127
    const int ch = tid & 3;        // 16B chunk within 64B k-window

    float4 fa[4];   // MODE 0 staging (2 rows x 2 float4)
    uint4  ua[2];   // MODE 1 staging (2 rows x 8 halves)

#define LD_A(it) do {                                                          \
    if (MODE == 0) {                                                           \
        const float* Ap = (const float*)Asrc;                                  \
        const float4* q0 = (const float4*)(Ap + (rb + r0)*256 + (it)*32 + ch*8);\
        fa[0] = q0[0]; fa[1] = q0[1];                                          \
        const float4* q1 = (const float4*)(Ap + (rb + r1)*256 + (it)*32 + ch*8);\
        fa[2] = q1[0]; fa[3] = q1[1];                                          \
    } else {                                                                   \
        const uint4* Ap = (const uint4*)Asrc;                                  \
        ua[0] = Ap[(rb + r0)*32 + (it)*4 + ch];                                \
        ua[1] = Ap[(rb + r1)*32 + (it)*4 + ch];                                \
    } } while (0)

#define ST_A(it, sA) do {                                                      \
    if (MODE == 0) {                                                           \
        __half2 h0 = __floats2half2_rn(fa[0].x, fa[0].y);                      \
        __half2 h1 = __floats2half2_rn(fa[0].z, fa[0].w);                      \
        __half2 h2 = __floats2half2_rn(fa[1].x, fa[1].y);                      \
        __half2 h3 = __floats2half2_rn(fa[1].z, fa[1].w);                      \
        asm volatile("st.shared.v4.b32 [%0], {%1,%2,%3,%4};"                   \
            :: "r"((sA) + r0*LDT + ch*16),                                     \
               "r"(*(uint32_t*)&h0), "r"(*(uint32_t*)&h1),                     \
               "r"(*(uint32_t*)&h2), "r"(*(uint32_t*)&h3));                    \
        h0 = __floats2half2_rn(fa[2].x, fa[2].y);                              \
        h1 = __floats2half2_rn(fa[2].z, fa[2].w);                              \
        h2 = __floats2half2_rn(fa[3].x, fa[3].y);                              \
        h3 = __floats2half2_rn(fa[3].z, fa[3].w);                              \
        asm volatile("st.shared.v4.b32 [%0], {%1,%2,%3,%4};"                   \
            :: "r"((sA) + r1*LDT + ch*16),                                     \
               "r"(*(uint32_t*)&h0), "r"(*(uint32_t*)&h1),                     \
               "r"(*(uint32_t*)&h2), "r"(*(uint32_t*)&h3));                    \
    } else {                                                                   \
        __half2 s2 = __float2half2_rn(sclS[r0*8 + (it)]);                      \
        uint4 t0 = ua[0]; __half2* hp = (__half2*)&t0;                         \
        hp[0]=__hmul2(hp[0],s2); hp[1]=__hmul2(hp[1],s2);                      \
        hp[2]=__hmul2(hp[2],s2); hp[3]=__hmul2(hp[3],s2);                      \
        asm volatile("st.shared.v4.b32 [%0], {%1,%2,%3,%4};"                   \
            :: "r"((sA) + r0*LDT + ch*16),                                     \
               "r"(t0.x), "r"(t0.y), "r"(t0.z), "r"(t0.w));                    \
        s2 = __float2half2_rn(sclS[r1*8 + (it)]);                              \
        uint4 t1 = ua[1]; hp = (__half2*)&t1;                                  \
        hp[0]=__hmul2(hp[0],s2); hp[1]=__hmul2(hp[1],s2);                      \
        hp[2]=__hmul2(hp[2],s2); hp[3]=__hmul2(hp[3],s2);                      \
        asm volatile("st.shared.v4.b32 [%0], {%1,%2,%3,%4};"                   \
            :: "r"((sA) + r1*LDT + ch*16),                                     \
               "r"(t1.x), "r"(t1.y), "r"(t1.z), "r"(t1.w));                    \
    } } while (0)

#define CP_B(it, sB) do {                                                      \
    _Pragma("unroll")                                                          \
    for (int j = 0; j < 4; j++) {                                              \
        int n = (tid + j*256) >> 2;                                            \
        cp_async16((sB) + n*LDT + ch*16, W16 + n*256 + (it)*32 + ch*8);        \
    } } while (0)

    float c[4][8][4];
    #pragma unroll
    for (int mt = 0; mt < 4; mt++)
        #pragma unroll
        for (int nt = 0; nt < 8; nt++)
            #pragma unroll
            for (int j = 0; j < 4; j++) c[mt][nt][j] = 0.0f;

    // ldmatrix per-lane address components
    const uint32_t a_off = (uint32_t)((wm*64 + (lane & 15))*LDT + (lane >> 4)*16);
    const uint32_t b_off = (uint32_t)((wn*64 + (lane & 7) + (lane >> 4)*8)*LDT
                                      + ((lane >> 3) & 1)*16);

    // ---------------- prologue: prime A(0) and B(0), B(1)
    LD_A(0);
    CP_B(0, sB0);
    asm volatile("cp.async.commit_group;" ::: "memory");
    CP_B(1, sB1);
    asm volatile("cp.async.commit_group;" ::: "memory");
    ST_A(0, sA0);
    asm volatile("cp.async.wait_group 1;" ::: "memory");   // B(0) arrived
    __syncthreads();

    uint32_t sAcur = sA0, sAnxt = sA1;
    uint32_t sBcur = sB0, sBnxt = sB1, sBnn = sB2;

    // ---------------- main loop: 8 k-iters of 32
    #pragma unroll 1
    for (int it = 0; it < 8; it++) {
        if (it < 7) LD_A(it + 1);
        if (it < 6) {
            CP_B(it + 2, sBnn);
            asm volatile("cp.async.commit_group;" ::: "memory");
        }

        #pragma unroll
        for (int ks = 0; ks < 2; ks++) {
            uint32_t a[4][4], bfr[4][4];
            const uint32_t ab = sAcur + a_off + ks*32;
            #pragma unroll
            for (int mt = 0; mt < 4; mt++) ldsm_x4(a[mt], ab + mt*16*LDT);
            const uint32_t bb = sBcur + b_off + ks*32;
            #pragma unroll
            for (int ntp = 0; ntp < 4; ntp++) ldsm_x4(bfr[ntp], bb + ntp*16*LDT);
            #pragma unroll
            for (int mt = 0; mt < 4; mt++)
                #pragma unroll
                for (int nt = 0; nt < 8; nt++)
                    mma16816(c[mt][nt], a[mt], &bfr[nt >> 1][(nt & 1)*2]);
        }

        if (it < 7) ST_A(it + 1, sAnxt);
        if (it < 6) {
            asm volatile("cp.async.wait_group 1;" ::: "memory"); // B(it+1) done
        } else if (it == 6) {
            asm volatile("cp.async.wait_group 0;" ::: "memory"); // B(7) done
        }
        __syncthreads();

        uint32_t t = sAcur; sAcur = sAnxt; sAnxt = t;
        t = sBcur; sBcur = sBnxt; sBnxt = sBnn; sBnn = t;
    }

    // ---------------- epilogue
    const int mrow = lane >> 2;
    const int ncol = (lane & 3)*2;
    float p[2][8];
    if (MODE == 0) {
        #pragma unroll
        for (int hl = 0; hl < 2; hl++)
            #pragma unroll
            for (int rs = 0; rs < 8; rs++) p[hl][rs] = 0.0f;
    }

    #pragma unroll
    for (int mt = 0; mt < 4; mt++) {
        #pragma unroll
        for (int nt = 0; nt < 8; nt++) {
            const int m = wm*64 + mt*16 + mrow;
            const int n = wn*64 + nt*8 + ncol;
            const float b0 = biasS[n], b1 = biasS[n+1];
            float* cc = c[mt][nt];
            if (MODE == 0) {
                float v0 = cc[0] + b0, v1 = cc[1] + b1;
                float v2 = cc[2] + b0, v3 = cc[3] + b1;
                __half2 h0 = __floats2half2_rn(v0, v1);
                __half2 h1 = __floats2half2_rn(v2, v3);
                unsigned short* o = (unsigned short*)Cout;
                *(uint32_t*)(o + (rb + m)*256 + n)     = *(uint32_t*)&h0;
                *(uint32_t*)(o + (rb + m + 8)*256 + n) = *(uint32_t*)&h1;
                // fused scores partials: head = n/32, rows are n-positions
                const int hl = nt >> 2;
                const float q0 = qs[n], q1 = qs[n+1];
                p[hl][mt*2+0] += v0*q0 + v1*q1;
                p[hl][mt*2+1] += v2*q0 + v3*q1;
            } else {
                float* o = (float*)Cout;
                float2 o0 = { mishf(cc[0] + b0), mishf(cc[1] + b1) };
                float2 o1 = { mishf(cc[2] + b0), mishf(cc[3] + b1) };
                *(float2*)(o + (rb + m)*256 + n)     = o0;
                *(float2*)(o + (rb + m + 8)*256 + n) = o1;
            }
        }
    }

    if (MODE == 0) {
        // reduce partials over the 4 lanes sharing a row (lane^1, lane^2)
        #pragma unroll
        for (int o = 1; o <= 2; o <<= 1)
            #pragma unroll
            for (int hl = 0; hl < 2; hl++)
                #pragma unroll
                for (int rs = 0; rs < 8; rs++)
                    p[hl][rs] += __shfl_xor_sync(0xffffffffu, p[hl][rs], o);
        if ((lane & 3) == 0) {
            #pragma unroll
            for (int mt = 0; mt < 4; mt++)
                #pragma unroll
                for (int half = 0; half < 2; half++)
                    #pragma unroll
                    for (int hl = 0; hl < 2; hl++) {
                        int nloc = wm*64 + mt*16 + mrow + half*8;
                        sred[nloc*8 + wn*2 + hl] = p[hl][mt*2 + half];
                    }
        }
        __syncthreads();
        const int bq = (int)(rb >> 14), mq = (int)((rb >> 7) & 127);
        const float scale = 0.17677669529663687f;   // 1/sqrt(32)
        #pragma unroll
        for (int i = tid; i < 1024; i += 256) {
            int n = i >> 3, h = i & 7;
            Sglob[((((long long)bq*8 + h)*128 + mq)*128) + n] = sred[n*8 + h]*scale;
        }
    }
#undef LD_A
#undef ST_A
#undef CP_B
}

// ---------------------------------------------------------------------------
// W fp32 -> fp16 prep
// ---------------------------------------------------------------------------
__global__ void prep_w16(const float* __restrict__ Wk, const float* __restrict__ We,
                         unsigned short* __restrict__ Wk16, unsigned short* __restrict__ We16)
{
    int i = blockIdx.x * 256 + threadIdx.x;
    __half a = __float2half(Wk[i]);
    __half b = __float2half(We[i]);
    Wk16[i] = *(unsigned short*)&a;
    We16[i] = *(unsigned short*)&b;
}

// ---------------------------------------------------------------------------
// dm[b,m,n] = mask[b,n] ? exp(-lam*dist[b,m,n]) : 0   (one-time, dedup x8 heads)
// ---------------------------------------------------------------------------
__global__ void dm_kernel(const float* __restrict__ dist, const float* __restrict__ mask,
                          const float* __restrict__ lam, float* __restrict__ dm)
{
    int idx = blockIdx.x * 256 + threadIdx.x;   // over B*M*M = 131072
    int b = idx >> 14, n = idx & 127;
    float mv = mask[b*128 + n];
    dm[idx] = (mv != 0.0f) ? __expf(-lam[0]*dist[idx]) : 0.0f;
}

// ---------------------------------------------------------------------------
// small SIMT GEMM body (q/v/node_out): 64x64x16 tile, fp32
// ---------------------------------------------------------------------------
template<int MODE>   // 0 = identity, 1 = mish
__device__ __forceinline__ void gemm_body(
    const float* __restrict__ A, const float* __restrict__ W,
    const float* __restrict__ bias, float* __restrict__ C,
    int bx, int by)
{
    __shared__ float As[16][64];
    __shared__ float Ws[16][64];
    const int tid = threadIdx.x;
    const long long rb = (long long)by * 64;
    const int cb = bx * 64;
    const int lr = tid >> 2, lk = (tid & 3) << 2;
    const int tr = tid & 15, tc = tid >> 4;
    float acc[4][4] = {};
    for (int k0 = 0; k0 < 256; k0 += 16) {
        float4 av = *reinterpret_cast<const float4*>(&A[(rb + lr)*256 + k0 + lk]);
        As[lk+0][lr] = av.x; As[lk+1][lr] = av.y; As[lk+2][lr] = av.z; As[lk+3][lr] = av.w;
        float4 wv = *reinterpret_cast<const float4*>(&W[(long long)(cb + lr)*256 + k0 + lk]);
        Ws[lk+0][lr] = wv.x; Ws[lk+1][lr] = wv.y; Ws[lk+2][lr] = wv.z; Ws[lk+3][lr] = wv.w;
        __syncthreads();
        #pragma unroll
        for (int kk = 0; kk < 16; kk++) {
            float4 a4 = *reinterpret_cast<const float4*>(&As[kk][tr*4]);
            float4 w4 = *reinterpret_cast<const float4*>(&Ws[kk][tc*4]);
            float a[4] = {a4.x, a4.y, a4.z, a4.w};
            float w[4] = {w4.x, w4.y, w4.z, w4.w};
            #pragma unroll
            for (int i = 0; i < 4; i++)
                #pragma unroll
                for (int j = 0; j < 4; j++) acc[i][j] += a[i]*w[j];
        }
        __syncthreads();
    }
    #pragma unroll
    for (int i = 0; i < 4; i++) {
        long long row = rb + tr*4 + i;
        #pragma unroll
        for (int j = 0; j < 4; j++) {
            int col = cb + tc*4 + j;
            float v = acc[i][j] + bias[col];
            if (MODE == 1) v = mishf(v);
            C[row*256 + col] = v;
        }
    }
}

__global__ __launch_bounds__(256) void proj_qv(
    const float* __restrict__ node,
    const float* __restrict__ Wq, const float* __restrict__ bq,
    const float* __restrict__ Wv, const float* __restrict__ bv,
    float* __restrict__ q, float* __restrict__ v)
{
    if (blockIdx.z == 0) gemm_body<0>(node, Wq, bq, q, blockIdx.x, blockIdx.y);
    else                 gemm_body<0>(node, Wv, bv, v, blockIdx.x, blockIdx.y);
}

__global__ __launch_bounds__(256) void node_out_gemm(
    const float* __restrict__ nh, const float* __restrict__ Wn,
    const float* __restrict__ bn, float* __restrict__ C)
{
    gemm_body<1>(nh, Wn, bn, C, blockIdx.x, blockIdx.y);
}

// ---------------------------------------------------------------------------
// softmax / message / node_hidden v2.
// grid (4 m-chunks, 64 bh); 256 threads. Per CTA: 32 rows of one (b,h).
// E matrices computed in-place (1 expf per cell); dm precomputed.
// msg written head-innermost: msg_t[(b,m,n), h].
// ---------------------------------------------------------------------------
#define SROW_ST 129
#define SCOL_ST 33
#define VS_ST   36
#define SMEM_MSG ((32*SROW_ST + 128*SCOL_ST + 128*VS_ST) * 4)   // 51840 B

__global__ __launch_bounds__(256) void message_kernel(
    const float* __restrict__ S, const float* __restrict__ v,
    const float* __restrict__ dm, const float* __restrict__ mask,
    float* __restrict__ msg_t, float* __restrict__ nh)
{
    extern __shared__ float sm[];
    float* Srow = sm;                          // 32 x 129 (rows m0..m0+31)
    float* Scol = Srow + 32*SROW_ST;           // 128 x 33 (S[:, m0..m0+31])
    float* vs   = Scol + 128*SCOL_ST;          // 128 x 36
    __shared__ float msk[128];
    __shared__ float rmaxS[32], rsumS[32], cmaxS[32], csumS[32];

    const int bh = blockIdx.y;
    const int b = bh >> 3, h = bh & 7;
    const int m0 = blockIdx.x * 32;
    const int tid = threadIdx.x;

    const float* Sg = S + (long long)bh*128*128;
    #pragma unroll 2
    for (int idx = tid; idx < 32*128; idx += 256)
        Srow[(idx >> 7)*SROW_ST + (idx & 127)] = Sg[(m0 + (idx >> 7))*128 + (idx & 127)];
    #pragma unroll 2
    for (int idx = tid; idx < 128*32; idx += 256)
        Scol[(idx >> 5)*SCOL_ST + (idx & 31)] = Sg[(idx >> 5)*128 + m0 + (idx & 31)];
    #pragma unroll 2
    for (int idx = tid; idx < 128*32; idx += 256)
        vs[(idx >> 5)*VS_ST + (idx & 31)] = v[((b*128 + (idx >> 5))*256) + h*32 + (idx & 31)];
    if (tid < 128) msk[tid] = mask[b*128 + tid];
    __syncthreads();

    const int r  = tid >> 3;       // 0..31 : local row (or local col)
    const int sl = tid & 7;        // 8 lanes cooperate per row

    // ---- pass A: maxes (row r of chunk; column m0+r)
    float rmax = -1e30f, cmax = -1e30f;
    #pragma unroll 4
    for (int i = 0; i < 16; i++) {
        int n = sl + i*8;
        if (msk[n] != 0.0f) {
            rmax = fmaxf(rmax, Srow[r*SROW_ST + n]);
            cmax = fmaxf(cmax, Scol[n*SCOL_ST + r]);
        }
    }
    #pragma unroll
    for (int o = 1; o <= 4; o <<= 1) {
        rmax = fmaxf(rmax, __shfl_xor_sync(0xffffffffu, rmax, o));
        cmax = fmaxf(cmax, __shfl_xor_sync(0xffffffffu, cmax, o));
    }
    if (sl == 0) { rmaxS[r] = rmax; cmaxS[r] = cmax; }
    __syncthreads();

    // ---- pass B: E = exp(S - max) in place (masked -> 0), sums
    rmax = rmaxS[r]; cmax = cmaxS[r];
    float rsum = 0.0f, csum = 0.0f;
    #pragma unroll 4
    for (int i = 0; i < 16; i++) {
        int n = sl + i*8;
        float er = 0.0f, ec = 0.0f;
        if (msk[n] != 0.0f) {
            er = __expf(Srow[r*SROW_ST + n] - rmax);
            ec = __expf(Scol[n*SCOL_ST + r] - cmax);
        }
        Srow[r*SROW_ST + n] = er;  rsum += er;
        Scol[n*SCOL_ST + r] = ec;  csum += ec;
    }
    #pragma unroll
    for (int o = 1; o <= 4; o <<= 1) {
        rsum += __shfl_xor_sync(0xffffffffu, rsum, o);
        csum += __shfl_xor_sync(0xffffffffu, csum, o);
    }
    if (sl == 0) { rsumS[r] = 1.0f / rsum; csumS[r] = 1.0f / csum; }
    __syncthreads();

    // ---- pass C: msg (overwrite Srow in place), write msg_t global
    const float inv_rs = rsumS[r], inv_cs = csumS[r];
    const int mglob = m0 + r;
    const float* dmr = dm + ((long long)b*128 + mglob)*128;
    float* mtr = msg_t + (((long long)b*128 + mglob)*128)*8 + h;
    #pragma unroll 4
    for (int i = 0; i < 16; i++) {
        int n = sl + i*8;
        float eo = Srow[r*SROW_ST + n] * inv_rs;
        float ei = Scol[n*SCOL_ST + r] * inv_cs;
        float t  = (n == mglob) ? ei : (eo + ei);
        float mv = t * dmr[n];
        Srow[r*SROW_ST + n] = mv;
        mtr[n*8] = mv;
    }
    __syncthreads();

    // ---- pass D: node_hidden partial rows (complete: full n-range here)
    const int d0 = sl*4;
    float a0 = 0.0f, a1 = 0.0f, a2 = 0.0f, a3 = 0.0f;
    #pragma unroll 4
    for (int n = 0; n < 128; n++) {
        float mv = Srow[r*SROW_ST + n];
        float4 vv = *(const float4*)&vs[n*VS_ST + d0];
        a0 += mv*vv.x; a1 += mv*vv.y; a2 += mv*vv.z; a3 += mv*vv.w;
    }
    float* nhr = nh + ((long long)(b*128 + mglob))*256 + h*32 + d0;
    *(float4*)nhr = make_float4(a0, a1, a2, a3);
}

// ---------------------------------------------------------------------------
extern "C" void kernel_launch(void* const* d_in, const int* in_sizes, int n_in,
                              void* d_out, int out_size)
{
    const float* node = (const float*)d_in[0];
    const float* edge = (const float*)d_in[1];
    const float* dist = (const float*)d_in[2];
    const float* mask = (const float*)d_in[3];
    const float* lam  = (const float*)d_in[4];
    const float* Wq   = (const float*)d_in[5];
    const float* bq   = (const float*)d_in[6];
    const float* Wk   = (const float*)d_in[7];
    const float* bk   = (const float*)d_in[8];
    const float* Wv   = (const float*)d_in[9];
    const float* bv   = (const float*)d_in[10];
    const float* Wn   = (const float*)d_in[11];
    const float* bn   = (const float*)d_in[12];
    const float* We   = (const float*)d_in[13];
    const float* be   = (const float*)d_in[14];

    float* out = (float*)d_out;
    float* node_out = out;
    float* edge_out = out + B_*M_*HID_;

    float *q, *v, *S, *msg, *nh, *dm;
    unsigned short *k16, *Wk16, *We16;
    cudaGetSymbolAddress((void**)&q,    g_q);
    cudaGetSymbolAddress((void**)&v,    g_v);
    cudaGetSymbolAddress((void**)&S,    g_S);
    cudaGetSymbolAddress((void**)&msg,  g_msg);
    cudaGetSymbolAddress((void**)&nh,   g_nh);
    cudaGetSymbolAddress((void**)&dm,   g_dm);
    cudaGetSymbolAddress((void**)&k16,  g_k16);
    cudaGetSymbolAddress((void**)&Wk16, g_Wk16);
    cudaGetSymbolAddress((void**)&We16, g_We16);

    cudaFuncSetAttribute(message_kernel,
                         cudaFuncAttributeMaxDynamicSharedMemorySize, SMEM_MSG);
    cudaFuncSetAttribute(mma_gemm<0>,
                         cudaFuncAttributeMaxDynamicSharedMemorySize, SMEM_MMA);
    cudaFuncSetAttribute(mma_gemm<1>,
                         cudaFuncAttributeMaxDynamicSharedMemorySize, SMEM_MMA);

    prep_w16<<<256, 256>>>(Wk, We, Wk16, We16);
    dm_kernel<<<512, 256>>>(dist, mask, lam, dm);
    proj_qv<<<dim3(4, 16, 2), 256>>>(node, Wq, bq, Wv, bv, q, v);
    mma_gemm<0><<<1024, 256, SMEM_MMA>>>(edge, Wk16, bk, k16, nullptr, q, S);
    message_kernel<<<dim3(4, 64), 256, SMEM_MSG>>>(S, v, dm, mask, msg, nh);
    node_out_gemm<<<dim3(4, 16), 256>>>(nh, Wn, bn, node_out);
    mma_gemm<1><<<1024, 256, SMEM_MMA>>>(k16, We16, be, edge_out, msg, nullptr, nullptr);
}

// round 8
// speedup vs baseline: 5.1359x; 1.1236x over previous
#include <cuda_runtime.h>
#include <cuda_fp16.h>
#include <math.h>
#include <stdint.h>

#define B_   8
#define M_   128
#define HID_ 256
#define NH_  8
#define D_   32

// ---------------- scratch (device globals: no allocations allowed) ----------
__device__ float g_q  [B_*M_*HID_];
__device__ float g_v  [B_*M_*HID_];
__device__ float g_nh [B_*M_*HID_];
__device__ float g_S  [B_*NH_*M_*M_];
__device__ float g_msg[B_*M_*M_*NH_];               // layout [(b,m,n), h]
__device__ float g_dm [B_*M_*M_];                   // mask * exp(-lam*dist)
__device__ unsigned short g_k16 [(long long)B_*M_*M_*HID_];   // fp16 k (67 MB)
__device__ unsigned short g_Wk16[HID_*HID_];
__device__ unsigned short g_We16[HID_*HID_];

// ---------------------------- helpers ---------------------------------------
__device__ __forceinline__ uint32_t smem_u32(const void* p) {
    uint32_t a;
    asm("{ .reg .u64 t; cvta.to.shared.u64 t, %1; cvt.u32.u64 %0, t; }" : "=r"(a) : "l"(p));
    return a;
}
__device__ __forceinline__ void cp_async16(uint32_t dst, const void* src) {
    asm volatile("cp.async.cg.shared.global [%0], [%1], 16;" :: "r"(dst), "l"(src));
}
__device__ __forceinline__ void ldsm_x4(uint32_t* r, uint32_t addr) {
    asm volatile("ldmatrix.sync.aligned.m8n8.x4.shared.b16 {%0,%1,%2,%3}, [%4];"
        : "=r"(r[0]), "=r"(r[1]), "=r"(r[2]), "=r"(r[3]) : "r"(addr));
}
__device__ __forceinline__ void mma16816(float* c, const uint32_t* a, const uint32_t* b) {
    asm volatile("mma.sync.aligned.m16n8k16.row.col.f32.f16.f16.f32 "
        "{%0,%1,%2,%3}, {%4,%5,%6,%7}, {%8,%9}, {%0,%1,%2,%3};"
        : "+f"(c[0]), "+f"(c[1]), "+f"(c[2]), "+f"(c[3])
        : "r"(a[0]), "r"(a[1]), "r"(a[2]), "r"(a[3]), "r"(b[0]), "r"(b[1]));
}
__device__ __forceinline__ float mishf(float x) {
    if (x > 20.0f) return x;
    float t = __expf(x);
    float u = t * (t + 2.0f);
    return x * __fdividef(u, u + 2.0f);
}

// ---------------------------------------------------------------------------
// HMMA GEMM: C[131072 x 256] = epi( A'[131072 x 256] @ W16^T + bias )
//   MODE 0 (k-proj):   A = fp32 edge -> cvt fp16; epi: +bias -> k16 (fp16)
//                      + FUSED SCORES: S[b,h,m,n] = scale * sum_col k*q
//   MODE 1 (edge-out): A = fp16 k scaled per (row, head=k-iter) by msg_t;
//                      epi: +bias, mish, store fp32
// Tile: BM=128 x BN=256 x BK=32. 512 threads (16 warps, 4x4), warp tile 32x64.
// B: 3-stage cp.async pipeline (wait_group 1). A: LDG->reg->STS double buffer.
// ---------------------------------------------------------------------------
#define LDT 80            // bytes per padded smem row (40 halves)
#define OFF_SCALE 0       // 1024 floats (MODE 1)
#define OFF_BIAS  4096    // 256 floats
#define OFF_QS    5120    // 256 floats (MODE 0)
#define OFF_SRED  6144    // 128*8 floats (MODE 0)
#define OFF_T     10240
#define ASZ (128*LDT)     // 10240
#define BSZ (256*LDT)     // 20480
#define SMEM_MMA (OFF_T + 2*ASZ + 3*BSZ)   // 92160

template<int MODE>
__global__ __launch_bounds__(512) void mma_gemm(
    const void* __restrict__ Asrc, const unsigned short* __restrict__ W16v,
    const float* __restrict__ bias, void* __restrict__ Cout,
    const float* __restrict__ msg_t,
    const float* __restrict__ qglob, float* __restrict__ Sglob)
{
    extern __shared__ __align__(128) char smem[];
    float* sclS  = (float*)(smem + OFF_SCALE);
    float* biasS = (float*)(smem + OFF_BIAS);
    float* qs    = (float*)(smem + OFF_QS);
    float* sred  = (float*)(smem + OFF_SRED);
    const uint32_t sb = smem_u32(smem);
    const uint32_t sA0 = sb + OFF_T;
    const uint32_t sA1 = sA0 + ASZ;
    const uint32_t sB0 = sA1 + ASZ;
    const uint32_t sB1 = sB0 + BSZ;
    const uint32_t sB2 = sB1 + BSZ;

    const int tid  = threadIdx.x;
    const int lane = tid & 31, warp = tid >> 5;      // warp 0..15
    const int wm = warp >> 2, wn = warp & 3;         // 4 x 4
    const long long rb = (long long)blockIdx.x * 128;
    const __half* W16 = (const __half*)W16v;

    if (tid < 256) biasS[tid] = bias[tid];
    if (MODE == 1) {
        // msg_t layout [(b,m,n), h]: rows rb..rb+127 x 8 heads, contiguous
        if (tid < 256) {
            const float4* ms = (const float4*)(msg_t + rb*8);
            ((float4*)sclS)[tid] = ms[tid];
        }
    } else {
        // this CTA covers rows (b, m, n=0..127): (b, m) fixed
        if (tid < 256) {
            int bq = (int)(rb >> 14), mq = (int)((rb >> 7) & 127);
            qs[tid] = qglob[((long long)bq*128 + mq)*256 + tid];
        }
    }
    __syncthreads();

    // per-thread A/B loader coordinates: 512 chunks of 16B per A tile
    const int r0 = tid >> 2;       // A row 0..127
    const int ch = tid & 3;        // 16B chunk within 64B k-window

    float4 fa[2];   // MODE 0 staging (1 chunk = 2 float4)
    uint4  ua;      // MODE 1 staging (1 chunk = 8 halves)

#define LD_A(it) do {                                                          \
    if (MODE == 0) {                                                           \
        const float* Ap = (const float*)Asrc;                                  \
        const float4* q0 = (const float4*)(Ap + (rb + r0)*256 + (it)*32 + ch*8);\
        fa[0] = q0[0]; fa[1] = q0[1];                                          \
    } else {                                                                   \
        const uint4* Ap = (const uint4*)Asrc;                                  \
        ua = Ap[(rb + r0)*32 + (it)*4 + ch];                                   \
    } } while (0)

#define ST_A(it, sA) do {                                                      \
    if (MODE == 0) {                                                           \
        __half2 h0 = __floats2half2_rn(fa[0].x, fa[0].y);                      \
        __half2 h1 = __floats2half2_rn(fa[0].z, fa[0].w);                      \
        __half2 h2 = __floats2half2_rn(fa[1].x, fa[1].y);                      \
        __half2 h3 = __floats2half2_rn(fa[1].z, fa[1].w);                      \
        asm volatile("st.shared.v4.b32 [%0], {%1,%2,%3,%4};"                   \
            :: "r"((sA) + r0*LDT + ch*16),                                     \
               "r"(*(uint32_t*)&h0), "r"(*(uint32_t*)&h1),                     \
               "r"(*(uint32_t*)&h2), "r"(*(uint32_t*)&h3));                    \
    } else {                                                                   \
        __half2 s2 = __float2half2_rn(sclS[r0*8 + (it)]);                      \
        uint4 t0 = ua; __half2* hp = (__half2*)&t0;                            \
        hp[0]=__hmul2(hp[0],s2); hp[1]=__hmul2(hp[1],s2);                      \
        hp[2]=__hmul2(hp[2],s2); hp[3]=__hmul2(hp[3],s2);                      \
        asm volatile("st.shared.v4.b32 [%0], {%1,%2,%3,%4};"                   \
            :: "r"((sA) + r0*LDT + ch*16),                                     \
               "r"(t0.x), "r"(t0.y), "r"(t0.z), "r"(t0.w));                    \
    } } while (0)

#define CP_B(it, sB) do {                                                      \
    _Pragma("unroll")                                                          \
    for (int j = 0; j < 2; j++) {                                              \
        int n = (tid + j*512) >> 2;                                            \
        cp_async16((sB) + n*LDT + ch*16, W16 + n*256 + (it)*32 + ch*8);        \
    } } while (0)

    float c[2][8][4];
    #pragma unroll
    for (int mt = 0; mt < 2; mt++)
        #pragma unroll
        for (int nt = 0; nt < 8; nt++)
            #pragma unroll
            for (int j = 0; j < 4; j++) c[mt][nt][j] = 0.0f;

    // ldmatrix per-lane address components
    const uint32_t a_off = (uint32_t)((wm*32 + (lane & 15))*LDT + (lane >> 4)*16);
    const uint32_t b_off = (uint32_t)((wn*64 + (lane & 7) + (lane >> 4)*8)*LDT
                                      + ((lane >> 3) & 1)*16);

    // ---------------- prologue: prime A(0) and B(0), B(1)
    LD_A(0);
    CP_B(0, sB0);
    asm volatile("cp.async.commit_group;" ::: "memory");
    CP_B(1, sB1);
    asm volatile("cp.async.commit_group;" ::: "memory");
    ST_A(0, sA0);
    asm volatile("cp.async.wait_group 1;" ::: "memory");   // B(0) arrived
    __syncthreads();

    uint32_t sAcur = sA0, sAnxt = sA1;
    uint32_t sBcur = sB0, sBnxt = sB1, sBnn = sB2;

    // ---------------- main loop: 8 k-iters of 32
    #pragma unroll 1
    for (int it = 0; it < 8; it++) {
        if (it < 7) LD_A(it + 1);
        if (it < 6) {
            CP_B(it + 2, sBnn);
            asm volatile("cp.async.commit_group;" ::: "memory");
        }

        #pragma unroll
        for (int ks = 0; ks < 2; ks++) {
            uint32_t a[2][4], bfr[4][4];
            const uint32_t ab = sAcur + a_off + ks*32;
            #pragma unroll
            for (int mt = 0; mt < 2; mt++) ldsm_x4(a[mt], ab + mt*16*LDT);
            const uint32_t bb = sBcur + b_off + ks*32;
            #pragma unroll
            for (int ntp = 0; ntp < 4; ntp++) ldsm_x4(bfr[ntp], bb + ntp*16*LDT);
            #pragma unroll
            for (int mt = 0; mt < 2; mt++)
                #pragma unroll
                for (int nt = 0; nt < 8; nt++)
                    mma16816(c[mt][nt], a[mt], &bfr[nt >> 1][(nt & 1)*2]);
        }

        if (it < 7) ST_A(it + 1, sAnxt);
        if (it < 6) {
            asm volatile("cp.async.wait_group 1;" ::: "memory"); // B(it+1) done
        } else if (it == 6) {
            asm volatile("cp.async.wait_group 0;" ::: "memory"); // B(7) done
        }
        __syncthreads();

        uint32_t t = sAcur; sAcur = sAnxt; sAnxt = t;
        t = sBcur; sBcur = sBnxt; sBnxt = sBnn; sBnn = t;
    }

    // ---------------- epilogue
    const int mrow = lane >> 2;
    const int ncol = (lane & 3)*2;
    float p[2][4];
    if (MODE == 0) {
        #pragma unroll
        for (int hl = 0; hl < 2; hl++)
            #pragma unroll
            for (int rs = 0; rs < 4; rs++) p[hl][rs] = 0.0f;
    }

    #pragma unroll
    for (int mt = 0; mt < 2; mt++) {
        #pragma unroll
        for (int nt = 0; nt < 8; nt++) {
            const int m = wm*32 + mt*16 + mrow;
            const int n = wn*64 + nt*8 + ncol;
            const float b0 = biasS[n], b1 = biasS[n+1];
            float* cc = c[mt][nt];
            if (MODE == 0) {
                float v0 = cc[0] + b0, v1 = cc[1] + b1;
                float v2 = cc[2] + b0, v3 = cc[3] + b1;
                __half2 h0 = __floats2half2_rn(v0, v1);
                __half2 h1 = __floats2half2_rn(v2, v3);
                unsigned short* o = (unsigned short*)Cout;
                *(uint32_t*)(o + (rb + m)*256 + n)     = *(uint32_t*)&h0;
                *(uint32_t*)(o + (rb + m + 8)*256 + n) = *(uint32_t*)&h1;
                // fused scores partials: head = n/32, rows are n-positions
                const int hl = nt >> 2;
                const float q0 = qs[n], q1 = qs[n+1];
                p[hl][mt*2+0] += v0*q0 + v1*q1;
                p[hl][mt*2+1] += v2*q0 + v3*q1;
            } else {
                float* o = (float*)Cout;
                float2 o0 = { mishf(cc[0] + b0), mishf(cc[1] + b1) };
                float2 o1 = { mishf(cc[2] + b0), mishf(cc[3] + b1) };
                *(float2*)(o + (rb + m)*256 + n)     = o0;
                *(float2*)(o + (rb + m + 8)*256 + n) = o1;
            }
        }
    }

    if (MODE == 0) {
        // reduce partials over the 4 lanes sharing a row (lane^1, lane^2)
        #pragma unroll
        for (int o = 1; o <= 2; o <<= 1)
            #pragma unroll
            for (int hl = 0; hl < 2; hl++)
                #pragma unroll
                for (int rs = 0; rs < 4; rs++)
                    p[hl][rs] += __shfl_xor_sync(0xffffffffu, p[hl][rs], o);
        if ((lane & 3) == 0) {
            #pragma unroll
            for (int mt = 0; mt < 2; mt++)
                #pragma unroll
                for (int half = 0; half < 2; half++)
                    #pragma unroll
                    for (int hl = 0; hl < 2; hl++) {
                        int nloc = wm*32 + mt*16 + mrow + half*8;
                        sred[nloc*8 + wn*2 + hl] = p[hl][mt*2 + half];
                    }
        }
        __syncthreads();
        const int bq = (int)(rb >> 14), mq = (int)((rb >> 7) & 127);
        const float scale = 0.17677669529663687f;   // 1/sqrt(32)
        #pragma unroll
        for (int i = tid; i < 1024; i += 512) {
            int n = i >> 3, h = i & 7;
            Sglob[((((long long)bq*8 + h)*128 + mq)*128) + n] = sred[n*8 + h]*scale;
        }
    }
#undef LD_A
#undef ST_A
#undef CP_B
}

// ---------------------------------------------------------------------------
// W fp32 -> fp16 prep
// ---------------------------------------------------------------------------
__global__ void prep_w16(const float* __restrict__ Wk, const float* __restrict__ We,
                         unsigned short* __restrict__ Wk16, unsigned short* __restrict__ We16)
{
    int i = blockIdx.x * 256 + threadIdx.x;
    __half a = __float2half(Wk[i]);
    __half b = __float2half(We[i]);
    Wk16[i] = *(unsigned short*)&a;
    We16[i] = *(unsigned short*)&b;
}

// ---------------------------------------------------------------------------
// dm[b,m,n] = mask[b,n] ? exp(-lam*dist[b,m,n]) : 0   (one-time, dedup x8 heads)
// ---------------------------------------------------------------------------
__global__ void dm_kernel(const float* __restrict__ dist, const float* __restrict__ mask,
                          const float* __restrict__ lam, float* __restrict__ dm)
{
    int idx = blockIdx.x * 256 + threadIdx.x;   // over B*M*M = 131072
    int b = idx >> 14, n = idx & 127;
    float mv = mask[b*128 + n];
    dm[idx] = (mv != 0.0f) ? __expf(-lam[0]*dist[idx]) : 0.0f;
}

// ---------------------------------------------------------------------------
// small SIMT GEMM body (q/v/node_out): 64x64x16 tile, fp32
// ---------------------------------------------------------------------------
template<int MODE>   // 0 = identity, 1 = mish
__device__ __forceinline__ void gemm_body(
    const float* __restrict__ A, const float* __restrict__ W,
    const float* __restrict__ bias, float* __restrict__ C,
    int bx, int by)
{
    __shared__ float As[16][64];
    __shared__ float Ws[16][64];
    const int tid = threadIdx.x;
    const long long rb = (long long)by * 64;
    const int cb = bx * 64;
    const int lr = tid >> 2, lk = (tid & 3) << 2;
    const int tr = tid & 15, tc = tid >> 4;
    float acc[4][4] = {};
    for (int k0 = 0; k0 < 256; k0 += 16) {
        float4 av = *reinterpret_cast<const float4*>(&A[(rb + lr)*256 + k0 + lk]);
        As[lk+0][lr] = av.x; As[lk+1][lr] = av.y; As[lk+2][lr] = av.z; As[lk+3][lr] = av.w;
        float4 wv = *reinterpret_cast<const float4*>(&W[(long long)(cb + lr)*256 + k0 + lk]);
        Ws[lk+0][lr] = wv.x; Ws[lk+1][lr] = wv.y; Ws[lk+2][lr] = wv.z; Ws[lk+3][lr] = wv.w;
        __syncthreads();
        #pragma unroll
        for (int kk = 0; kk < 16; kk++) {
            float4 a4 = *reinterpret_cast<const float4*>(&As[kk][tr*4]);
            float4 w4 = *reinterpret_cast<const float4*>(&Ws[kk][tc*4]);
            float a[4] = {a4.x, a4.y, a4.z, a4.w};
            float w[4] = {w4.x, w4.y, w4.z, w4.w};
            #pragma unroll
            for (int i = 0; i < 4; i++)
                #pragma unroll
                for (int j = 0; j < 4; j++) acc[i][j] += a[i]*w[j];
        }
        __syncthreads();
    }
    #pragma unroll
    for (int i = 0; i < 4; i++) {
        long long row = rb + tr*4 + i;
        #pragma unroll
        for (int j = 0; j < 4; j++) {
            int col = cb + tc*4 + j;
            float v = acc[i][j] + bias[col];
            if (MODE == 1) v = mishf(v);
            C[row*256 + col] = v;
        }
    }
}

__global__ __launch_bounds__(256) void proj_qv(
    const float* __restrict__ node,
    const float* __restrict__ Wq, const float* __restrict__ bq,
    const float* __restrict__ Wv, const float* __restrict__ bv,
    float* __restrict__ q, float* __restrict__ v)
{
    if (blockIdx.z == 0) gemm_body<0>(node, Wq, bq, q, blockIdx.x, blockIdx.y);
    else                 gemm_body<0>(node, Wv, bv, v, blockIdx.x, blockIdx.y);
}

__global__ __launch_bounds__(256) void node_out_gemm(
    const float* __restrict__ nh, const float* __restrict__ Wn,
    const float* __restrict__ bn, float* __restrict__ C)
{
    gemm_body<1>(nh, Wn, bn, C, blockIdx.x, blockIdx.y);
}

// ---------------------------------------------------------------------------
// softmax / message / node_hidden v2.
// grid (4 m-chunks, 64 bh); 256 threads. Per CTA: 32 rows of one (b,h).
// E matrices computed in-place (1 expf per cell); dm precomputed.
// msg written head-innermost: msg_t[(b,m,n), h].
// ---------------------------------------------------------------------------
#define SROW_ST 129
#define SCOL_ST 33
#define VS_ST   36
#define SMEM_MSG ((32*SROW_ST + 128*SCOL_ST + 128*VS_ST) * 4)   // 51840 B

__global__ __launch_bounds__(256) void message_kernel(
    const float* __restrict__ S, const float* __restrict__ v,
    const float* __restrict__ dm, const float* __restrict__ mask,
    float* __restrict__ msg_t, float* __restrict__ nh)
{
    extern __shared__ float sm[];
    float* Srow = sm;                          // 32 x 129 (rows m0..m0+31)
    float* Scol = Srow + 32*SROW_ST;           // 128 x 33 (S[:, m0..m0+31])
    float* vs   = Scol + 128*SCOL_ST;          // 128 x 36
    __shared__ float msk[128];
    __shared__ float rmaxS[32], rsumS[32], cmaxS[32], csumS[32];

    const int bh = blockIdx.y;
    const int b = bh >> 3, h = bh & 7;
    const int m0 = blockIdx.x * 32;
    const int tid = threadIdx.x;

    const float* Sg = S + (long long)bh*128*128;
    #pragma unroll 2
    for (int idx = tid; idx < 32*128; idx += 256)
        Srow[(idx >> 7)*SROW_ST + (idx & 127)] = Sg[(m0 + (idx >> 7))*128 + (idx & 127)];
    #pragma unroll 2
    for (int idx = tid; idx < 128*32; idx += 256)
        Scol[(idx >> 5)*SCOL_ST + (idx & 31)] = Sg[(idx >> 5)*128 + m0 + (idx & 31)];
    #pragma unroll 2
    for (int idx = tid; idx < 128*32; idx += 256)
        vs[(idx >> 5)*VS_ST + (idx & 31)] = v[((b*128 + (idx >> 5))*256) + h*32 + (idx & 31)];
    if (tid < 128) msk[tid] = mask[b*128 + tid];
    __syncthreads();

    const int r  = tid >> 3;       // 0..31 : local row (or local col)
    const int sl = tid & 7;        // 8 lanes cooperate per row

    // ---- pass A: maxes (row r of chunk; column m0+r)
    float rmax = -1e30f, cmax = -1e30f;
    #pragma unroll 4
    for (int i = 0; i < 16; i++) {
        int n = sl + i*8;
        if (msk[n] != 0.0f) {
            rmax = fmaxf(rmax, Srow[r*SROW_ST + n]);
            cmax = fmaxf(cmax, Scol[n*SCOL_ST + r]);
        }
    }
    #pragma unroll
    for (int o = 1; o <= 4; o <<= 1) {
        rmax = fmaxf(rmax, __shfl_xor_sync(0xffffffffu, rmax, o));
        cmax = fmaxf(cmax, __shfl_xor_sync(0xffffffffu, cmax, o));
    }
    if (sl == 0) { rmaxS[r] = rmax; cmaxS[r] = cmax; }
    __syncthreads();

    // ---- pass B: E = exp(S - max) in place (masked -> 0), sums
    rmax = rmaxS[r]; cmax = cmaxS[r];
    float rsum = 0.0f, csum = 0.0f;
    #pragma unroll 4
    for (int i = 0; i < 16; i++) {
        int n = sl + i*8;
        float er = 0.0f, ec = 0.0f;
        if (msk[n] != 0.0f) {
            er = __expf(Srow[r*SROW_ST + n] - rmax);
            ec = __expf(Scol[n*SCOL_ST + r] - cmax);
        }
        Srow[r*SROW_ST + n] = er;  rsum += er;
        Scol[n*SCOL_ST + r] = ec;  csum += ec;
    }
    #pragma unroll
    for (int o = 1; o <= 4; o <<= 1) {
        rsum += __shfl_xor_sync(0xffffffffu, rsum, o);
        csum += __shfl_xor_sync(0xffffffffu, csum, o);
    }
    if (sl == 0) { rsumS[r] = 1.0f / rsum; csumS[r] = 1.0f / csum; }
    __syncthreads();

    // ---- pass C: msg (overwrite Srow in place), write msg_t global
    const float inv_rs = rsumS[r], inv_cs = csumS[r];
    const int mglob = m0 + r;
    const float* dmr = dm + ((long long)b*128 + mglob)*128;
    float* mtr = msg_t + (((long long)b*128 + mglob)*128)*8 + h;
    #pragma unroll 4
    for (int i = 0; i < 16; i++) {
        int n = sl + i*8;
        float eo = Srow[r*SROW_ST + n] * inv_rs;
        float ei = Scol[n*SCOL_ST + r] * inv_cs;
        float t  = (n == mglob) ? ei : (eo + ei);
        float mv = t * dmr[n];
        Srow[r*SROW_ST + n] = mv;
        mtr[n*8] = mv;
    }
    __syncthreads();

    // ---- pass D: node_hidden partial rows (complete: full n-range here)
    const int d0 = sl*4;
    float a0 = 0.0f, a1 = 0.0f, a2 = 0.0f, a3 = 0.0f;
    #pragma unroll 4
    for (int n = 0; n < 128; n++) {
        float mv = Srow[r*SROW_ST + n];
        float4 vv = *(const float4*)&vs[n*VS_ST + d0];
        a0 += mv*vv.x; a1 += mv*vv.y; a2 += mv*vv.z; a3 += mv*vv.w;
    }
    float* nhr = nh + ((long long)(b*128 + mglob))*256 + h*32 + d0;
    *(float4*)nhr = make_float4(a0, a1, a2, a3);
}

// ---------------------------------------------------------------------------
extern "C" void kernel_launch(void* const* d_in, const int* in_sizes, int n_in,
                              void* d_out, int out_size)
{
    const float* node = (const float*)d_in[0];
    const float* edge = (const float*)d_in[1];
    const float* dist = (const float*)d_in[2];
    const float* mask = (const float*)d_in[3];
    const float* lam  = (const float*)d_in[4];
    const float* Wq   = (const float*)d_in[5];
    const float* bq   = (const float*)d_in[6];
    const float* Wk   = (const float*)d_in[7];
    const float* bk   = (const float*)d_in[8];
    const float* Wv   = (const float*)d_in[9];
    const float* bv   = (const float*)d_in[10];
    const float* Wn   = (const float*)d_in[11];
    const float* bn   = (const float*)d_in[12];
    const float* We   = (const float*)d_in[13];
    const float* be   = (const float*)d_in[14];

    float* out = (float*)d_out;
    float* node_out = out;
    float* edge_out = out + B_*M_*HID_;

    float *q, *v, *S, *msg, *nh, *dm;
    unsigned short *k16, *Wk16, *We16;
    cudaGetSymbolAddress((void**)&q,    g_q);
    cudaGetSymbolAddress((void**)&v,    g_v);
    cudaGetSymbolAddress((void**)&S,    g_S);
    cudaGetSymbolAddress((void**)&msg,  g_msg);
    cudaGetSymbolAddress((void**)&nh,   g_nh);
    cudaGetSymbolAddress((void**)&dm,   g_dm);
    cudaGetSymbolAddress((void**)&k16,  g_k16);
    cudaGetSymbolAddress((void**)&Wk16, g_Wk16);
    cudaGetSymbolAddress((void**)&We16, g_We16);

    cudaFuncSetAttribute(message_kernel,
                         cudaFuncAttributeMaxDynamicSharedMemorySize, SMEM_MSG);
    cudaFuncSetAttribute(mma_gemm<0>,
                         cudaFuncAttributeMaxDynamicSharedMemorySize, SMEM_MMA);
    cudaFuncSetAttribute(mma_gemm<1>,
                         cudaFuncAttributeMaxDynamicSharedMemorySize, SMEM_MMA);

    prep_w16<<<256, 256>>>(Wk, We, Wk16, We16);
    dm_kernel<<<512, 256>>>(dist, mask, lam, dm);
    proj_qv<<<dim3(4, 16, 2), 256>>>(node, Wq, bq, Wv, bv, q, v);
    mma_gemm<0><<<1024, 512, SMEM_MMA>>>(edge, Wk16, bk, k16, nullptr, q, S);
    message_kernel<<<dim3(4, 64), 256, SMEM_MSG>>>(S, v, dm, mask, msg, nh);
    mma_gemm<1><<<1024, 512, SMEM_MMA>>>(k16, We16, be, edge_out, msg, nullptr, nullptr);
    node_out_gemm<<<dim3(4, 16), 256>>>(nh, Wn, bn, node_out);
}